// round 8
// baseline (speedup 1.0000x reference)
#include <cuda_runtime.h>
#include <stdint.h>

#define Lq     2048
#define EMB    1024
#define NHEAD  16
#define HD     64
#define NT     (Lq / 64)                       // key tiles
#define MP_WORDS (NHEAD * Lq * (Lq / 32))      // packed mask words

// Scratch (allocation-free rule: device globals)
__device__ float    g_Q[Lq * EMB];
__device__ float    g_K[Lq * EMB];
__device__ float    g_V[Lq * EMB];
__device__ float    g_A[Lq * EMB];
__device__ uint32_t g_Mp[MP_WORDS];            // bit-packed mask (8 MB)

__device__ __forceinline__ float to_tf32(float x) {
    float r; asm("cvt.rna.tf32.f32 %0, %1;" : "=f"(r) : "f"(x)); return r;
}

// m16n8k8 tf32 HMMA, D (+)= A*B, row.col
__device__ __forceinline__ void mma_tf32(float d[4], const float a0, const float a1,
                                         const float a2, const float a3,
                                         const float b0, const float b1) {
    asm volatile(
        "mma.sync.aligned.m16n8k8.row.col.f32.tf32.tf32.f32 "
        "{%0,%1,%2,%3}, {%4,%5,%6,%7}, {%8,%9}, {%0,%1,%2,%3};\n"
        : "+f"(d[0]), "+f"(d[1]), "+f"(d[2]), "+f"(d[3])
        : "r"(__float_as_uint(a0)), "r"(__float_as_uint(a1)),
          "r"(__float_as_uint(a2)), "r"(__float_as_uint(a3)),
          "r"(__float_as_uint(b0)), "r"(__float_as_uint(b1)));
}

// ===========================================================================
// Mask bit-pack: int32[H*L*L] -> u32 bits (ballot). Bit i of word w = col bit.
// ===========================================================================
__global__ __launch_bounds__(256)
void maskpack_kernel(const int* __restrict__ mask, uint32_t* __restrict__ mp)
{
    const int lane = threadIdx.x & 31;
    const int wgid = (blockIdx.x * blockDim.x + threadIdx.x) >> 5;
    const int nw   = (gridDim.x * blockDim.x) >> 5;
    for (int w = wgid; w < MP_WORDS; w += nw) {
        int v = mask[(size_t)w * 32 + lane];
        uint32_t bits = __ballot_sync(0xffffffffu, v != 0);
        if (lane == 0) mp[w] = bits;
    }
}

// ===========================================================================
// Warp-MMA tf32 NT GEMM, 3xTF32, tile 128x64, 8 warps (2m x 4n), warp 64x16.
// 256 CTAs -> all SMs busy, 2 CTAs/SM overlap staging with compute.
// ===========================================================================
__global__ __launch_bounds__(256, 2)
void gemm_mma_kernel(const float* __restrict__ A, const float* __restrict__ B,
                     float* __restrict__ C)
{
    __shared__ float As_hi[128][20], As_lo[128][20];
    __shared__ float Bs_hi[64][20],  Bs_lo[64][20];

    const int tid  = threadIdx.x;
    const int lane = tid & 31;
    const int wid  = tid >> 5;
    const int g    = lane >> 2;
    const int t4   = lane & 3;
    const int wm   = (wid & 1) * 64;
    const int wn   = (wid >> 1) * 16;

    const int bm = blockIdx.y * 128;
    const int bn = blockIdx.x * 64;

    const int lr  = tid >> 2;
    const int lc4 = (tid & 3) * 4;
    const float* a0p = A + (size_t)(bm + lr) * EMB + lc4;
    const float* a1p = a0p + (size_t)64 * EMB;
    const float* b0p = B + (size_t)(bn + lr) * EMB + lc4;

    float d[4][2][4];
    #pragma unroll
    for (int i = 0; i < 4; ++i)
        #pragma unroll
        for (int j = 0; j < 2; ++j)
            #pragma unroll
            for (int r = 0; r < 4; ++r) d[i][j][r] = 0.f;

    float4 pa0 = *(const float4*)a0p;
    float4 pa1 = *(const float4*)a1p;
    float4 pb0 = *(const float4*)b0p;

    for (int c = 0; c < EMB / 16; ++c) {
        __syncthreads();
        {
            float4 hi, lo;
            hi = make_float4(to_tf32(pa0.x), to_tf32(pa0.y), to_tf32(pa0.z), to_tf32(pa0.w));
            lo = make_float4(to_tf32(pa0.x - hi.x), to_tf32(pa0.y - hi.y),
                             to_tf32(pa0.z - hi.z), to_tf32(pa0.w - hi.w));
            *(float4*)&As_hi[lr][lc4] = hi; *(float4*)&As_lo[lr][lc4] = lo;

            hi = make_float4(to_tf32(pa1.x), to_tf32(pa1.y), to_tf32(pa1.z), to_tf32(pa1.w));
            lo = make_float4(to_tf32(pa1.x - hi.x), to_tf32(pa1.y - hi.y),
                             to_tf32(pa1.z - hi.z), to_tf32(pa1.w - hi.w));
            *(float4*)&As_hi[lr + 64][lc4] = hi; *(float4*)&As_lo[lr + 64][lc4] = lo;

            hi = make_float4(to_tf32(pb0.x), to_tf32(pb0.y), to_tf32(pb0.z), to_tf32(pb0.w));
            lo = make_float4(to_tf32(pb0.x - hi.x), to_tf32(pb0.y - hi.y),
                             to_tf32(pb0.z - hi.z), to_tf32(pb0.w - hi.w));
            *(float4*)&Bs_hi[lr][lc4] = hi; *(float4*)&Bs_lo[lr][lc4] = lo;
        }
        if (c + 1 < EMB / 16) {
            pa0 = *(const float4*)(a0p + (c + 1) * 16);
            pa1 = *(const float4*)(a1p + (c + 1) * 16);
            pb0 = *(const float4*)(b0p + (c + 1) * 16);
        }
        __syncthreads();

        #pragma unroll
        for (int ks = 0; ks < 2; ++ks) {
            const int k0 = ks * 8 + t4;
            float bhi[2][2], blo[2][2];
            #pragma unroll
            for (int ni = 0; ni < 2; ++ni) {
                int n = wn + ni * 8 + g;
                bhi[ni][0] = Bs_hi[n][k0];     bhi[ni][1] = Bs_hi[n][k0 + 4];
                blo[ni][0] = Bs_lo[n][k0];     blo[ni][1] = Bs_lo[n][k0 + 4];
            }
            #pragma unroll
            for (int mi = 0; mi < 4; ++mi) {
                int m = wm + mi * 16 + g;
                float ah0 = As_hi[m][k0],     ah1 = As_hi[m + 8][k0];
                float ah2 = As_hi[m][k0 + 4], ah3 = As_hi[m + 8][k0 + 4];
                float al0 = As_lo[m][k0],     al1 = As_lo[m + 8][k0];
                float al2 = As_lo[m][k0 + 4], al3 = As_lo[m + 8][k0 + 4];
                #pragma unroll
                for (int ni = 0; ni < 2; ++ni) {
                    mma_tf32(d[mi][ni], ah0, ah1, ah2, ah3, bhi[ni][0], bhi[ni][1]);
                    mma_tf32(d[mi][ni], ah0, ah1, ah2, ah3, blo[ni][0], blo[ni][1]);
                    mma_tf32(d[mi][ni], al0, al1, al2, al3, bhi[ni][0], bhi[ni][1]);
                }
            }
        }
    }

    #pragma unroll
    for (int mi = 0; mi < 4; ++mi) {
        int m = bm + wm + mi * 16 + g;
        #pragma unroll
        for (int ni = 0; ni < 2; ++ni) {
            int n = bn + wn + ni * 8 + 2 * t4;
            *(float2*)(C + (size_t)m * EMB + n)       = make_float2(d[mi][ni][0], d[mi][ni][1]);
            *(float2*)(C + (size_t)(m + 8) * EMB + n) = make_float2(d[mi][ni][2], d[mi][ni][3]);
        }
    }
}

// ===========================================================================
// Tensor-core flash attention v3: R6 smem layout + DOUBLE BUFFER + register
// prefetch of K/V + bit-packed mask (4 prefetched LDG.32/thread/tile).
// ===========================================================================
#define KP 76
#define VP 72
#define KBUF (64 * KP)
#define VBUF (64 * VP)
#define OFF_KL (2 * KBUF * 4)
#define OFF_VS (4 * KBUF * 4)
#define ATTN_SMEM (4 * KBUF * 4 + 2 * VBUF * 4)   // 114688

__global__ __launch_bounds__(256, 1)
void attn_mma_kernel(const float* __restrict__ Q, const float* __restrict__ Kg,
                     const float* __restrict__ Vg, const uint32_t* __restrict__ Mp,
                     float* __restrict__ O)
{
    extern __shared__ char smem[];
    float* KH = (float*)(smem);
    float* KL = (float*)(smem + OFF_KL);
    float* VS = (float*)(smem + OFF_VS);

    const int tid  = threadIdx.x;
    const int lane = tid & 31;
    const int wid  = tid >> 5;
    const int g    = lane >> 2;
    const int t4   = lane & 3;
    const int h    = blockIdx.y;
    const int qb   = blockIdx.x;
    const int hb   = h * HD;
    const int row0 = qb * 128 + wid * 16;

    // ---- Q fragments: scaled by 1/8, split hi/lo, resident all kernel ----
    float qh[8][4], ql[8][4];
    #pragma unroll
    for (int ks = 0; ks < 8; ++ks) {
        int d0 = hb + 8 * ks + t4;
        float v0 = Q[(size_t)(row0 + g)     * EMB + d0]     * 0.125f;
        float v1 = Q[(size_t)(row0 + g + 8) * EMB + d0]     * 0.125f;
        float v2 = Q[(size_t)(row0 + g)     * EMB + d0 + 4] * 0.125f;
        float v3 = Q[(size_t)(row0 + g + 8) * EMB + d0 + 4] * 0.125f;
        qh[ks][0] = to_tf32(v0); ql[ks][0] = to_tf32(v0 - qh[ks][0]);
        qh[ks][1] = to_tf32(v1); ql[ks][1] = to_tf32(v1 - qh[ks][1]);
        qh[ks][2] = to_tf32(v2); ql[ks][2] = to_tf32(v2 - qh[ks][2]);
        qh[ks][3] = to_tf32(v3); ql[ks][3] = to_tf32(v3 - qh[ks][3]);
    }

    float o[8][4];
    #pragma unroll
    for (int ni = 0; ni < 8; ++ni)
        #pragma unroll
        for (int r = 0; r < 4; ++r) o[ni][r] = 0.f;
    float m0 = -1.0e30f, m1 = -1.0e30f;
    float l0 = 0.f, l1 = 0.f;

    // staging coordinates
    const int key = tid >> 2;          // key row this thread stages
    const int qq  = tid & 3;           // 16-dim segment

    const float* kbase = Kg + (size_t)key * EMB + hb;
    const float* vbase = Vg + (size_t)key * EMB + hb;
    const int rbase = wid * 16 + g;
    const uint32_t* mp0 = Mp + ((size_t)h * Lq + qb * 128 + rbase) * (Lq / 32);
    const uint32_t* mp1 = mp0 + 8 * (Lq / 32);

    // ---- prologue: prefetch tile 0 ----
    float4 pk0 = *(const float4*)(kbase + 8 * qq);
    float4 pk1 = *(const float4*)(kbase + 8 * qq + 4);
    float4 pk2 = *(const float4*)(kbase + 8 * (qq + 4));
    float4 pk3 = *(const float4*)(kbase + 8 * (qq + 4) + 4);
    float4 pv0 = *(const float4*)(vbase + qq * 16);
    float4 pv1 = *(const float4*)(vbase + qq * 16 + 4);
    float4 pv2 = *(const float4*)(vbase + qq * 16 + 8);
    float4 pv3 = *(const float4*)(vbase + qq * 16 + 12);
    uint32_t cm0 = mp0[0], cm1 = mp0[1], cm2 = mp1[0], cm3 = mp1[1];
    uint32_t nm0 = 0, nm1 = 0, nm2 = 0, nm3 = 0;

    #pragma unroll 1
    for (int kt = 0; kt < NT; ++kt) {
        const int b = kt & 1;
        float* Khb = KH + b * KBUF;
        float* Klb = KL + b * KBUF;
        float* Vsb = VS + b * VBUF;

        // ---- store staged tile (convert to tf32 hi/lo) ----
        {
            float4 hi, lo;
            hi = make_float4(to_tf32(pk0.x), to_tf32(pk0.y), to_tf32(pk0.z), to_tf32(pk0.w));
            lo = make_float4(to_tf32(pk0.x - hi.x), to_tf32(pk0.y - hi.y),
                             to_tf32(pk0.z - hi.z), to_tf32(pk0.w - hi.w));
            *(float4*)(Khb + key * KP + 8 * qq)     = hi;
            *(float4*)(Klb + key * KP + 8 * qq)     = lo;
            hi = make_float4(to_tf32(pk1.x), to_tf32(pk1.y), to_tf32(pk1.z), to_tf32(pk1.w));
            lo = make_float4(to_tf32(pk1.x - hi.x), to_tf32(pk1.y - hi.y),
                             to_tf32(pk1.z - hi.z), to_tf32(pk1.w - hi.w));
            *(float4*)(Khb + key * KP + 8 * qq + 4) = hi;
            *(float4*)(Klb + key * KP + 8 * qq + 4) = lo;
            hi = make_float4(to_tf32(pk2.x), to_tf32(pk2.y), to_tf32(pk2.z), to_tf32(pk2.w));
            lo = make_float4(to_tf32(pk2.x - hi.x), to_tf32(pk2.y - hi.y),
                             to_tf32(pk2.z - hi.z), to_tf32(pk2.w - hi.w));
            *(float4*)(Khb + key * KP + 8 * (qq + 4))     = hi;
            *(float4*)(Klb + key * KP + 8 * (qq + 4))     = lo;
            hi = make_float4(to_tf32(pk3.x), to_tf32(pk3.y), to_tf32(pk3.z), to_tf32(pk3.w));
            lo = make_float4(to_tf32(pk3.x - hi.x), to_tf32(pk3.y - hi.y),
                             to_tf32(pk3.z - hi.z), to_tf32(pk3.w - hi.w));
            *(float4*)(Khb + key * KP + 8 * (qq + 4) + 4) = hi;
            *(float4*)(Klb + key * KP + 8 * (qq + 4) + 4) = lo;

            *(float4*)(Vsb + key * VP + qq * 16) =
                make_float4(to_tf32(pv0.x), to_tf32(pv0.y), to_tf32(pv0.z), to_tf32(pv0.w));
            *(float4*)(Vsb + key * VP + qq * 16 + 4) =
                make_float4(to_tf32(pv1.x), to_tf32(pv1.y), to_tf32(pv1.z), to_tf32(pv1.w));
            *(float4*)(Vsb + key * VP + qq * 16 + 8) =
                make_float4(to_tf32(pv2.x), to_tf32(pv2.y), to_tf32(pv2.z), to_tf32(pv2.w));
            *(float4*)(Vsb + key * VP + qq * 16 + 12) =
                make_float4(to_tf32(pv3.x), to_tf32(pv3.y), to_tf32(pv3.z), to_tf32(pv3.w));
        }
        __syncthreads();

        // ---- prefetch tile kt+1 (latency hides under compute below) ----
        if (kt + 1 < NT) {
            const float* kn = kbase + (size_t)(kt + 1) * 64 * EMB;
            const float* vn = vbase + (size_t)(kt + 1) * 64 * EMB;
            pk0 = *(const float4*)(kn + 8 * qq);
            pk1 = *(const float4*)(kn + 8 * qq + 4);
            pk2 = *(const float4*)(kn + 8 * (qq + 4));
            pk3 = *(const float4*)(kn + 8 * (qq + 4) + 4);
            pv0 = *(const float4*)(vn + qq * 16);
            pv1 = *(const float4*)(vn + qq * 16 + 4);
            pv2 = *(const float4*)(vn + qq * 16 + 8);
            pv3 = *(const float4*)(vn + qq * 16 + 12);
            nm0 = mp0[(kt + 1) * 2];     nm1 = mp0[(kt + 1) * 2 + 1];
            nm2 = mp1[(kt + 1) * 2];     nm3 = mp1[(kt + 1) * 2 + 1];
        }

        // ================= S = Q K^T (3xTF32) =================
        float s[8][4];
        #pragma unroll
        for (int ni = 0; ni < 8; ++ni)
            #pragma unroll
            for (int r = 0; r < 4; ++r) s[ni][r] = 0.f;

        #pragma unroll
        for (int ks = 0; ks < 8; ++ks) {
            #pragma unroll
            for (int ni = 0; ni < 8; ++ni) {
                const float* kr = Khb + (8 * ni + g) * KP + 8 * ks + t4;
                const float* lr = Klb + (8 * ni + g) * KP + 8 * ks + t4;
                float b0h = kr[0], b1h = kr[4];
                float b0l = lr[0], b1l = lr[4];
                mma_tf32(s[ni], qh[ks][0], qh[ks][1], qh[ks][2], qh[ks][3], b0h, b1h);
                mma_tf32(s[ni], qh[ks][0], qh[ks][1], qh[ks][2], qh[ks][3], b0l, b1l);
                mma_tf32(s[ni], ql[ks][0], ql[ks][1], ql[ks][2], ql[ks][3], b0h, b1h);
            }
        }

        // ================= masked online softmax =================
        float tm0 = -1.0e30f, tm1 = -1.0e30f;
        #pragma unroll
        for (int ni = 0; ni < 8; ++ni) {
            uint32_t wr0 = (ni < 4) ? cm0 : cm1;
            uint32_t wr1 = (ni < 4) ? cm2 : cm3;
            int b2 = 8 * (ni & 3) + 2 * t4;
            tm0 = fmaxf(tm0, ((wr0 >> b2) & 1u)       ? -1.0e30f : s[ni][0]);
            tm0 = fmaxf(tm0, ((wr0 >> (b2 + 1)) & 1u) ? -1.0e30f : s[ni][1]);
            tm1 = fmaxf(tm1, ((wr1 >> b2) & 1u)       ? -1.0e30f : s[ni][2]);
            tm1 = fmaxf(tm1, ((wr1 >> (b2 + 1)) & 1u) ? -1.0e30f : s[ni][3]);
        }
        tm0 = fmaxf(tm0, __shfl_xor_sync(0xffffffffu, tm0, 1));
        tm0 = fmaxf(tm0, __shfl_xor_sync(0xffffffffu, tm0, 2));
        tm1 = fmaxf(tm1, __shfl_xor_sync(0xffffffffu, tm1, 1));
        tm1 = fmaxf(tm1, __shfl_xor_sync(0xffffffffu, tm1, 2));

        float mn0 = fmaxf(m0, tm0), mn1 = fmaxf(m1, tm1);
        float c0 = __expf(m0 - mn0), c1 = __expf(m1 - mn1);
        m0 = mn0; m1 = mn1;

        float rs0 = 0.f, rs1 = 0.f;
        #pragma unroll
        for (int ni = 0; ni < 8; ++ni) {
            uint32_t wr0 = (ni < 4) ? cm0 : cm1;
            uint32_t wr1 = (ni < 4) ? cm2 : cm3;
            int b2 = 8 * (ni & 3) + 2 * t4;
            float p0 = ((wr0 >> b2) & 1u)       ? 0.f : __expf(s[ni][0] - mn0);
            float p1 = ((wr0 >> (b2 + 1)) & 1u) ? 0.f : __expf(s[ni][1] - mn0);
            float p2 = ((wr1 >> b2) & 1u)       ? 0.f : __expf(s[ni][2] - mn1);
            float p3 = ((wr1 >> (b2 + 1)) & 1u) ? 0.f : __expf(s[ni][3] - mn1);
            s[ni][0] = p0; s[ni][1] = p1; s[ni][2] = p2; s[ni][3] = p3;
            rs0 += p0 + p1; rs1 += p2 + p3;
        }
        rs0 += __shfl_xor_sync(0xffffffffu, rs0, 1);
        rs0 += __shfl_xor_sync(0xffffffffu, rs0, 2);
        rs1 += __shfl_xor_sync(0xffffffffu, rs1, 1);
        rs1 += __shfl_xor_sync(0xffffffffu, rs1, 2);
        l0 = l0 * c0 + rs0;
        l1 = l1 * c1 + rs1;

        #pragma unroll
        for (int ni = 0; ni < 8; ++ni) {
            o[ni][0] *= c0; o[ni][1] *= c0;
            o[ni][2] *= c1; o[ni][3] *= c1;
        }

        // ================= O += P V (tf32) =================
        const int srcA = g * 4 + (t4 >> 1);
        const int srcB = srcA + 2;
        const int par  = t4 & 1;
        #pragma unroll
        for (int ki = 0; ki < 8; ++ki) {
            float e0 = __shfl_sync(0xffffffffu, s[ki][0], srcA);
            float o0 = __shfl_sync(0xffffffffu, s[ki][1], srcA);
            float e2 = __shfl_sync(0xffffffffu, s[ki][0], srcB);
            float o2 = __shfl_sync(0xffffffffu, s[ki][1], srcB);
            float e1 = __shfl_sync(0xffffffffu, s[ki][2], srcA);
            float o1 = __shfl_sync(0xffffffffu, s[ki][3], srcA);
            float e3 = __shfl_sync(0xffffffffu, s[ki][2], srcB);
            float o3 = __shfl_sync(0xffffffffu, s[ki][3], srcB);
            float a0 = to_tf32(par ? o0 : e0);
            float a1 = to_tf32(par ? o1 : e1);
            float a2 = to_tf32(par ? o2 : e2);
            float a3 = to_tf32(par ? o3 : e3);
            const float* v0 = Vsb + (8 * ki + t4) * VP + g;
            const float* v1 = Vsb + (8 * ki + t4 + 4) * VP + g;
            #pragma unroll
            for (int ni = 0; ni < 8; ++ni) {
                mma_tf32(o[ni], a0, a1, a2, a3, v0[8 * ni], v1[8 * ni]);
            }
        }

        cm0 = nm0; cm1 = nm1; cm2 = nm2; cm3 = nm3;
    }

    // ================= epilogue =================
    float inv0 = (l0 > 0.f) ? (1.f / l0) : 0.f;
    float inv1 = (l1 > 0.f) ? (1.f / l1) : 0.f;
    #pragma unroll
    for (int ni = 0; ni < 8; ++ni) {
        int col = hb + 8 * ni + 2 * t4;
        *(float2*)(O + (size_t)(row0 + g)     * EMB + col) =
            make_float2(o[ni][0] * inv0, o[ni][1] * inv0);
        *(float2*)(O + (size_t)(row0 + g + 8) * EMB + col) =
            make_float2(o[ni][2] * inv1, o[ni][3] * inv1);
    }
}

// ---------------------------------------------------------------------------
extern "C" void kernel_launch(void* const* d_in, const int* in_sizes, int n_in,
                              void* d_out, int out_size)
{
    const float* q    = (const float*)d_in[0];
    const float* k    = (const float*)d_in[1];
    const float* v    = (const float*)d_in[2];
    const int*   mask = (const int*)d_in[3];
    const float* Wq   = (const float*)d_in[4];
    const float* Wk   = (const float*)d_in[5];
    const float* Wv   = (const float*)d_in[6];
    const float* Wo   = (const float*)d_in[7];
    float*       out  = (float*)d_out;

    float *gQ, *gK, *gV, *gA;
    uint32_t* gMp;
    cudaGetSymbolAddress((void**)&gQ, g_Q);
    cudaGetSymbolAddress((void**)&gK, g_K);
    cudaGetSymbolAddress((void**)&gV, g_V);
    cudaGetSymbolAddress((void**)&gA, g_A);
    cudaGetSymbolAddress((void**)&gMp, g_Mp);

    cudaFuncSetAttribute(attn_mma_kernel,
                         cudaFuncAttributeMaxDynamicSharedMemorySize, ATTN_SMEM);

    maskpack_kernel<<<2048, 256>>>(mask, gMp);

    dim3 ggrid(EMB / 64, Lq / 128);    // (16, 16) = 256 CTAs

    gemm_mma_kernel<<<ggrid, 256>>>(q, Wq, gQ);
    gemm_mma_kernel<<<ggrid, 256>>>(k, Wk, gK);
    gemm_mma_kernel<<<ggrid, 256>>>(v, Wv, gV);

    dim3 agrid(Lq / 128, NHEAD);       // (16, 16)
    attn_mma_kernel<<<agrid, 256, ATTN_SMEM>>>(gQ, gK, gV, gMp, gA);

    gemm_mma_kernel<<<ggrid, 256>>>(gA, Wo, out);
}

// round 9
// speedup vs baseline: 1.3646x; 1.3646x over previous
#include <cuda_runtime.h>
#include <cuda_bf16.h>
#include <stdint.h>

#define Lq     2048
#define EMB    1024
#define NHEAD  16
#define HD     64
#define NT     (Lq / 64)                       // key tiles
#define MP_WORDS (NHEAD * Lq * (Lq / 32))      // packed mask words

// Scratch (allocation-free rule: device globals)
__device__ float    g_Q[Lq * EMB];
__device__ float    g_K[Lq * EMB];
__device__ float    g_V[Lq * EMB];
__device__ float    g_A[Lq * EMB];
__device__ uint32_t g_Mp[MP_WORDS];            // bit-packed mask (8 MB)

__device__ __forceinline__ float to_tf32(float x) {
    float r; asm("cvt.rna.tf32.f32 %0, %1;" : "=f"(r) : "f"(x)); return r;
}
__device__ __forceinline__ uint32_t smem_u32(const void* p) {
    uint32_t a;
    asm("{ .reg .u64 t; cvta.to.shared.u64 t, %1; cvt.u32.u64 %0, t; }" : "=r"(a) : "l"(p));
    return a;
}
// pack two floats -> bf16x2 (x0 in low half, x1 in high half)
__device__ __forceinline__ uint32_t cvt2bf(float x0, float x1) {
    uint32_t r;
    asm("cvt.rn.bf16x2.f32 %0, %1, %2;" : "=r"(r) : "f"(x1), "f"(x0));
    return r;
}
__device__ __forceinline__ float bf_lowf(uint32_t h)  { return __uint_as_float(h << 16); }
__device__ __forceinline__ float bf_highf(uint32_t h) { return __uint_as_float(h & 0xffff0000u); }

// m16n8k8 tf32 HMMA (attention path, unchanged)
__device__ __forceinline__ void mma_tf32(float d[4], const float a0, const float a1,
                                         const float a2, const float a3,
                                         const float b0, const float b1) {
    asm volatile(
        "mma.sync.aligned.m16n8k8.row.col.f32.tf32.tf32.f32 "
        "{%0,%1,%2,%3}, {%4,%5,%6,%7}, {%8,%9}, {%0,%1,%2,%3};\n"
        : "+f"(d[0]), "+f"(d[1]), "+f"(d[2]), "+f"(d[3])
        : "r"(__float_as_uint(a0)), "r"(__float_as_uint(a1)),
          "r"(__float_as_uint(a2)), "r"(__float_as_uint(a3)),
          "r"(__float_as_uint(b0)), "r"(__float_as_uint(b1)));
}

// m16n8k16 bf16 HMMA
__device__ __forceinline__ void mma_bf16(float d[4], const uint32_t a[4],
                                         const uint32_t b0, const uint32_t b1) {
    asm volatile(
        "mma.sync.aligned.m16n8k16.row.col.f32.bf16.bf16.f32 "
        "{%0,%1,%2,%3}, {%4,%5,%6,%7}, {%8,%9}, {%0,%1,%2,%3};\n"
        : "+f"(d[0]), "+f"(d[1]), "+f"(d[2]), "+f"(d[3])
        : "r"(a[0]), "r"(a[1]), "r"(a[2]), "r"(a[3]), "r"(b0), "r"(b1));
}

__device__ __forceinline__ void ldsm4(uint32_t r[4], uint32_t addr) {
    asm volatile("ldmatrix.sync.aligned.m8n8.x4.shared.b16 {%0,%1,%2,%3}, [%4];"
                 : "=r"(r[0]), "=r"(r[1]), "=r"(r[2]), "=r"(r[3]) : "r"(addr));
}

// ===========================================================================
// Mask bit-pack: int32[H*L*L] -> u32 bits (ballot).
// ===========================================================================
__global__ __launch_bounds__(256)
void maskpack_kernel(const int* __restrict__ mask, uint32_t* __restrict__ mp)
{
    const int lane = threadIdx.x & 31;
    const int wgid = (blockIdx.x * blockDim.x + threadIdx.x) >> 5;
    const int nw   = (gridDim.x * blockDim.x) >> 5;
    for (int w = wgid; w < MP_WORDS; w += nw) {
        int v = mask[(size_t)w * 32 + lane];
        uint32_t bits = __ballot_sync(0xffffffffu, v != 0);
        if (lane == 0) mp[w] = bits;
    }
}

// ===========================================================================
// bf16 3xsplit NT GEMM via m16n8k16 + ldmatrix.
// CTA tile 64x128, grid (8,32)=256 CTAs. 8 warps (2m x 4n), warp 32x32.
// K-chunk 16. Smem planes row stride 48B (conflict-free ldmatrix phases).
// ===========================================================================
__global__ __launch_bounds__(256, 2)
void gemm_mma_kernel(const float* __restrict__ A, const float* __restrict__ B,
                     float* __restrict__ C)
{
    __shared__ uint32_t Ah[64][12],  Al[64][12];    // 64 rows x 48B
    __shared__ uint32_t Bh[128][12], Bl[128][12];   // 128 rows x 48B

    const int tid  = threadIdx.x;
    const int lane = tid & 31;
    const int wid  = tid >> 5;
    const int g    = lane >> 2;
    const int t4   = lane & 3;
    const int wm   = (wid & 1) * 32;
    const int wn   = (wid >> 1) * 32;

    const int bm = blockIdx.y * 64;
    const int bn = blockIdx.x * 128;

    // loader coords
    const int ar = tid >> 2, ac = (tid & 3) * 4;   // A: 64 rows x 16 cols, 1 float4/thr
    const int br = tid >> 1, bc = (tid & 1) * 8;   // B: 128 rows x 16 cols, 2 float4/thr
    const float* ap = A + (size_t)(bm + ar) * EMB + ac;
    const float* bp = B + (size_t)(bn + br) * EMB + bc;

    // ldmatrix source addresses (fixed per kernel)
    const uint32_t sAh = smem_u32(Ah), sAl = smem_u32(Al);
    const uint32_t sBh = smem_u32(Bh), sBl = smem_u32(Bl);
    const int arow = lane & 15, akoff = (lane >> 4) * 16;
    const int brow = (lane & 7) + ((lane >> 4) << 3);
    const int bkoff = ((lane >> 3) & 1) * 16;
    uint32_t aAh[2], aAl[2], aBh[2], aBl[2];
    #pragma unroll
    for (int mi = 0; mi < 2; ++mi) {
        aAh[mi] = sAh + (wm + 16 * mi + arow) * 48 + akoff;
        aAl[mi] = sAl + (wm + 16 * mi + arow) * 48 + akoff;
    }
    #pragma unroll
    for (int p = 0; p < 2; ++p) {   // p=0 -> ni 0,1 ; p=1 -> ni 2,3
        aBh[p] = sBh + (wn + 16 * p + brow) * 48 + bkoff;
        aBl[p] = sBl + (wn + 16 * p + brow) * 48 + bkoff;
    }

    float d[2][4][4];
    #pragma unroll
    for (int i = 0; i < 2; ++i)
        #pragma unroll
        for (int j = 0; j < 4; ++j)
            #pragma unroll
            for (int r = 0; r < 4; ++r) d[i][j][r] = 0.f;

    float4 pa  = *(const float4*)ap;
    float4 pb0 = *(const float4*)bp;
    float4 pb1 = *(const float4*)(bp + 4);

    #pragma unroll 1
    for (int c = 0; c < EMB / 16; ++c) {
        __syncthreads();
        // ---- split & store chunk ----
        {
            uint32_t h0 = cvt2bf(pa.x, pa.y);
            uint32_t h1 = cvt2bf(pa.z, pa.w);
            uint32_t l0 = cvt2bf(pa.x - bf_lowf(h0), pa.y - bf_highf(h0));
            uint32_t l1 = cvt2bf(pa.z - bf_lowf(h1), pa.w - bf_highf(h1));
            *(uint2*)&Ah[ar][(tid & 3) * 2] = make_uint2(h0, h1);
            *(uint2*)&Al[ar][(tid & 3) * 2] = make_uint2(l0, l1);

            uint32_t bh0 = cvt2bf(pb0.x, pb0.y), bh1 = cvt2bf(pb0.z, pb0.w);
            uint32_t bh2 = cvt2bf(pb1.x, pb1.y), bh3 = cvt2bf(pb1.z, pb1.w);
            uint32_t bl0 = cvt2bf(pb0.x - bf_lowf(bh0), pb0.y - bf_highf(bh0));
            uint32_t bl1 = cvt2bf(pb0.z - bf_lowf(bh1), pb0.w - bf_highf(bh1));
            uint32_t bl2 = cvt2bf(pb1.x - bf_lowf(bh2), pb1.y - bf_highf(bh2));
            uint32_t bl3 = cvt2bf(pb1.z - bf_lowf(bh3), pb1.w - bf_highf(bh3));
            *(uint4*)&Bh[br][(tid & 1) * 4] = make_uint4(bh0, bh1, bh2, bh3);
            *(uint4*)&Bl[br][(tid & 1) * 4] = make_uint4(bl0, bl1, bl2, bl3);
        }
        // prefetch next chunk
        if (c + 1 < EMB / 16) {
            pa  = *(const float4*)(ap + (c + 1) * 16);
            pb0 = *(const float4*)(bp + (c + 1) * 16);
            pb1 = *(const float4*)(bp + (c + 1) * 16 + 4);
        }
        __syncthreads();

        // ---- fragments via ldmatrix ----
        uint32_t fah[2][4], fal[2][4], fbh[2][4], fbl[2][4];
        #pragma unroll
        for (int mi = 0; mi < 2; ++mi) { ldsm4(fah[mi], aAh[mi]); ldsm4(fal[mi], aAl[mi]); }
        #pragma unroll
        for (int p = 0; p < 2; ++p)    { ldsm4(fbh[p], aBh[p]);   ldsm4(fbl[p], aBl[p]); }

        // ---- MMAs: 2mi x 4ni x 3 ----
        #pragma unroll
        for (int mi = 0; mi < 2; ++mi) {
            #pragma unroll
            for (int ni = 0; ni < 4; ++ni) {
                const int p = ni >> 1, q = (ni & 1) * 2;
                uint32_t b0h = fbh[p][q], b1h = fbh[p][q + 1];
                uint32_t b0l = fbl[p][q], b1l = fbl[p][q + 1];
                mma_bf16(d[mi][ni], fah[mi], b0h, b1h);
                mma_bf16(d[mi][ni], fah[mi], b0l, b1l);
                mma_bf16(d[mi][ni], fal[mi], b0h, b1h);
            }
        }
    }

    // ---- epilogue ----
    #pragma unroll
    for (int mi = 0; mi < 2; ++mi) {
        int m = bm + wm + mi * 16 + g;
        #pragma unroll
        for (int ni = 0; ni < 4; ++ni) {
            int n = bn + wn + ni * 8 + 2 * t4;
            *(float2*)(C + (size_t)m * EMB + n)       = make_float2(d[mi][ni][0], d[mi][ni][1]);
            *(float2*)(C + (size_t)(m + 8) * EMB + n) = make_float2(d[mi][ni][2], d[mi][ni][3]);
        }
    }
}

// ===========================================================================
// Tensor-core flash attention (R8: double buffer + reg prefetch + bitmask).
// ===========================================================================
#define KP 76
#define VP 72
#define KBUF (64 * KP)
#define VBUF (64 * VP)
#define OFF_KL (2 * KBUF * 4)
#define OFF_VS (4 * KBUF * 4)
#define ATTN_SMEM (4 * KBUF * 4 + 2 * VBUF * 4)   // 114688

__global__ __launch_bounds__(256, 1)
void attn_mma_kernel(const float* __restrict__ Q, const float* __restrict__ Kg,
                     const float* __restrict__ Vg, const uint32_t* __restrict__ Mp,
                     float* __restrict__ O)
{
    extern __shared__ char smem[];
    float* KH = (float*)(smem);
    float* KL = (float*)(smem + OFF_KL);
    float* VS = (float*)(smem + OFF_VS);

    const int tid  = threadIdx.x;
    const int lane = tid & 31;
    const int wid  = tid >> 5;
    const int g    = lane >> 2;
    const int t4   = lane & 3;
    const int h    = blockIdx.y;
    const int qb   = blockIdx.x;
    const int hb   = h * HD;
    const int row0 = qb * 128 + wid * 16;

    float qh[8][4], ql[8][4];
    #pragma unroll
    for (int ks = 0; ks < 8; ++ks) {
        int d0 = hb + 8 * ks + t4;
        float v0 = Q[(size_t)(row0 + g)     * EMB + d0]     * 0.125f;
        float v1 = Q[(size_t)(row0 + g + 8) * EMB + d0]     * 0.125f;
        float v2 = Q[(size_t)(row0 + g)     * EMB + d0 + 4] * 0.125f;
        float v3 = Q[(size_t)(row0 + g + 8) * EMB + d0 + 4] * 0.125f;
        qh[ks][0] = to_tf32(v0); ql[ks][0] = to_tf32(v0 - qh[ks][0]);
        qh[ks][1] = to_tf32(v1); ql[ks][1] = to_tf32(v1 - qh[ks][1]);
        qh[ks][2] = to_tf32(v2); ql[ks][2] = to_tf32(v2 - qh[ks][2]);
        qh[ks][3] = to_tf32(v3); ql[ks][3] = to_tf32(v3 - qh[ks][3]);
    }

    float o[8][4];
    #pragma unroll
    for (int ni = 0; ni < 8; ++ni)
        #pragma unroll
        for (int r = 0; r < 4; ++r) o[ni][r] = 0.f;
    float m0 = -1.0e30f, m1 = -1.0e30f;
    float l0 = 0.f, l1 = 0.f;

    const int key = tid >> 2;
    const int qq  = tid & 3;

    const float* kbase = Kg + (size_t)key * EMB + hb;
    const float* vbase = Vg + (size_t)key * EMB + hb;
    const int rbase = wid * 16 + g;
    const uint32_t* mp0 = Mp + ((size_t)h * Lq + qb * 128 + rbase) * (Lq / 32);
    const uint32_t* mp1 = mp0 + 8 * (Lq / 32);

    float4 pk0 = *(const float4*)(kbase + 8 * qq);
    float4 pk1 = *(const float4*)(kbase + 8 * qq + 4);
    float4 pk2 = *(const float4*)(kbase + 8 * (qq + 4));
    float4 pk3 = *(const float4*)(kbase + 8 * (qq + 4) + 4);
    float4 pv0 = *(const float4*)(vbase + qq * 16);
    float4 pv1 = *(const float4*)(vbase + qq * 16 + 4);
    float4 pv2 = *(const float4*)(vbase + qq * 16 + 8);
    float4 pv3 = *(const float4*)(vbase + qq * 16 + 12);
    uint32_t cm0 = mp0[0], cm1 = mp0[1], cm2 = mp1[0], cm3 = mp1[1];
    uint32_t nm0 = 0, nm1 = 0, nm2 = 0, nm3 = 0;

    #pragma unroll 1
    for (int kt = 0; kt < NT; ++kt) {
        const int b = kt & 1;
        float* Khb = KH + b * KBUF;
        float* Klb = KL + b * KBUF;
        float* Vsb = VS + b * VBUF;

        {
            float4 hi, lo;
            hi = make_float4(to_tf32(pk0.x), to_tf32(pk0.y), to_tf32(pk0.z), to_tf32(pk0.w));
            lo = make_float4(to_tf32(pk0.x - hi.x), to_tf32(pk0.y - hi.y),
                             to_tf32(pk0.z - hi.z), to_tf32(pk0.w - hi.w));
            *(float4*)(Khb + key * KP + 8 * qq)     = hi;
            *(float4*)(Klb + key * KP + 8 * qq)     = lo;
            hi = make_float4(to_tf32(pk1.x), to_tf32(pk1.y), to_tf32(pk1.z), to_tf32(pk1.w));
            lo = make_float4(to_tf32(pk1.x - hi.x), to_tf32(pk1.y - hi.y),
                             to_tf32(pk1.z - hi.z), to_tf32(pk1.w - hi.w));
            *(float4*)(Khb + key * KP + 8 * qq + 4) = hi;
            *(float4*)(Klb + key * KP + 8 * qq + 4) = lo;
            hi = make_float4(to_tf32(pk2.x), to_tf32(pk2.y), to_tf32(pk2.z), to_tf32(pk2.w));
            lo = make_float4(to_tf32(pk2.x - hi.x), to_tf32(pk2.y - hi.y),
                             to_tf32(pk2.z - hi.z), to_tf32(pk2.w - hi.w));
            *(float4*)(Khb + key * KP + 8 * (qq + 4))     = hi;
            *(float4*)(Klb + key * KP + 8 * (qq + 4))     = lo;
            hi = make_float4(to_tf32(pk3.x), to_tf32(pk3.y), to_tf32(pk3.z), to_tf32(pk3.w));
            lo = make_float4(to_tf32(pk3.x - hi.x), to_tf32(pk3.y - hi.y),
                             to_tf32(pk3.z - hi.z), to_tf32(pk3.w - hi.w));
            *(float4*)(Khb + key * KP + 8 * (qq + 4) + 4) = hi;
            *(float4*)(Klb + key * KP + 8 * (qq + 4) + 4) = lo;

            *(float4*)(Vsb + key * VP + qq * 16) =
                make_float4(to_tf32(pv0.x), to_tf32(pv0.y), to_tf32(pv0.z), to_tf32(pv0.w));
            *(float4*)(Vsb + key * VP + qq * 16 + 4) =
                make_float4(to_tf32(pv1.x), to_tf32(pv1.y), to_tf32(pv1.z), to_tf32(pv1.w));
            *(float4*)(Vsb + key * VP + qq * 16 + 8) =
                make_float4(to_tf32(pv2.x), to_tf32(pv2.y), to_tf32(pv2.z), to_tf32(pv2.w));
            *(float4*)(Vsb + key * VP + qq * 16 + 12) =
                make_float4(to_tf32(pv3.x), to_tf32(pv3.y), to_tf32(pv3.z), to_tf32(pv3.w));
        }
        __syncthreads();

        if (kt + 1 < NT) {
            const float* kn = kbase + (size_t)(kt + 1) * 64 * EMB;
            const float* vn = vbase + (size_t)(kt + 1) * 64 * EMB;
            pk0 = *(const float4*)(kn + 8 * qq);
            pk1 = *(const float4*)(kn + 8 * qq + 4);
            pk2 = *(const float4*)(kn + 8 * (qq + 4));
            pk3 = *(const float4*)(kn + 8 * (qq + 4) + 4);
            pv0 = *(const float4*)(vn + qq * 16);
            pv1 = *(const float4*)(vn + qq * 16 + 4);
            pv2 = *(const float4*)(vn + qq * 16 + 8);
            pv3 = *(const float4*)(vn + qq * 16 + 12);
            nm0 = mp0[(kt + 1) * 2];     nm1 = mp0[(kt + 1) * 2 + 1];
            nm2 = mp1[(kt + 1) * 2];     nm3 = mp1[(kt + 1) * 2 + 1];
        }

        float s[8][4];
        #pragma unroll
        for (int ni = 0; ni < 8; ++ni)
            #pragma unroll
            for (int r = 0; r < 4; ++r) s[ni][r] = 0.f;

        #pragma unroll
        for (int ks = 0; ks < 8; ++ks) {
            #pragma unroll
            for (int ni = 0; ni < 8; ++ni) {
                const float* kr = Khb + (8 * ni + g) * KP + 8 * ks + t4;
                const float* lr = Klb + (8 * ni + g) * KP + 8 * ks + t4;
                float b0h = kr[0], b1h = kr[4];
                float b0l = lr[0], b1l = lr[4];
                mma_tf32(s[ni], qh[ks][0], qh[ks][1], qh[ks][2], qh[ks][3], b0h, b1h);
                mma_tf32(s[ni], qh[ks][0], qh[ks][1], qh[ks][2], qh[ks][3], b0l, b1l);
                mma_tf32(s[ni], ql[ks][0], ql[ks][1], ql[ks][2], ql[ks][3], b0h, b1h);
            }
        }

        float tm0 = -1.0e30f, tm1 = -1.0e30f;
        #pragma unroll
        for (int ni = 0; ni < 8; ++ni) {
            uint32_t wr0 = (ni < 4) ? cm0 : cm1;
            uint32_t wr1 = (ni < 4) ? cm2 : cm3;
            int b2 = 8 * (ni & 3) + 2 * t4;
            tm0 = fmaxf(tm0, ((wr0 >> b2) & 1u)       ? -1.0e30f : s[ni][0]);
            tm0 = fmaxf(tm0, ((wr0 >> (b2 + 1)) & 1u) ? -1.0e30f : s[ni][1]);
            tm1 = fmaxf(tm1, ((wr1 >> b2) & 1u)       ? -1.0e30f : s[ni][2]);
            tm1 = fmaxf(tm1, ((wr1 >> (b2 + 1)) & 1u) ? -1.0e30f : s[ni][3]);
        }
        tm0 = fmaxf(tm0, __shfl_xor_sync(0xffffffffu, tm0, 1));
        tm0 = fmaxf(tm0, __shfl_xor_sync(0xffffffffu, tm0, 2));
        tm1 = fmaxf(tm1, __shfl_xor_sync(0xffffffffu, tm1, 1));
        tm1 = fmaxf(tm1, __shfl_xor_sync(0xffffffffu, tm1, 2));

        float mn0 = fmaxf(m0, tm0), mn1 = fmaxf(m1, tm1);
        float c0 = __expf(m0 - mn0), c1 = __expf(m1 - mn1);
        m0 = mn0; m1 = mn1;

        float rs0 = 0.f, rs1 = 0.f;
        #pragma unroll
        for (int ni = 0; ni < 8; ++ni) {
            uint32_t wr0 = (ni < 4) ? cm0 : cm1;
            uint32_t wr1 = (ni < 4) ? cm2 : cm3;
            int b2 = 8 * (ni & 3) + 2 * t4;
            float p0 = ((wr0 >> b2) & 1u)       ? 0.f : __expf(s[ni][0] - mn0);
            float p1 = ((wr0 >> (b2 + 1)) & 1u) ? 0.f : __expf(s[ni][1] - mn0);
            float p2 = ((wr1 >> b2) & 1u)       ? 0.f : __expf(s[ni][2] - mn1);
            float p3 = ((wr1 >> (b2 + 1)) & 1u) ? 0.f : __expf(s[ni][3] - mn1);
            s[ni][0] = p0; s[ni][1] = p1; s[ni][2] = p2; s[ni][3] = p3;
            rs0 += p0 + p1; rs1 += p2 + p3;
        }
        rs0 += __shfl_xor_sync(0xffffffffu, rs0, 1);
        rs0 += __shfl_xor_sync(0xffffffffu, rs0, 2);
        rs1 += __shfl_xor_sync(0xffffffffu, rs1, 1);
        rs1 += __shfl_xor_sync(0xffffffffu, rs1, 2);
        l0 = l0 * c0 + rs0;
        l1 = l1 * c1 + rs1;

        #pragma unroll
        for (int ni = 0; ni < 8; ++ni) {
            o[ni][0] *= c0; o[ni][1] *= c0;
            o[ni][2] *= c1; o[ni][3] *= c1;
        }

        const int srcA = g * 4 + (t4 >> 1);
        const int srcB = srcA + 2;
        const int par  = t4 & 1;
        #pragma unroll
        for (int ki = 0; ki < 8; ++ki) {
            float e0 = __shfl_sync(0xffffffffu, s[ki][0], srcA);
            float o0 = __shfl_sync(0xffffffffu, s[ki][1], srcA);
            float e2 = __shfl_sync(0xffffffffu, s[ki][0], srcB);
            float o2 = __shfl_sync(0xffffffffu, s[ki][1], srcB);
            float e1 = __shfl_sync(0xffffffffu, s[ki][2], srcA);
            float o1 = __shfl_sync(0xffffffffu, s[ki][3], srcA);
            float e3 = __shfl_sync(0xffffffffu, s[ki][2], srcB);
            float o3 = __shfl_sync(0xffffffffu, s[ki][3], srcB);
            float a0 = to_tf32(par ? o0 : e0);
            float a1 = to_tf32(par ? o1 : e1);
            float a2 = to_tf32(par ? o2 : e2);
            float a3 = to_tf32(par ? o3 : e3);
            const float* v0 = Vsb + (8 * ki + t4) * VP + g;
            const float* v1 = Vsb + (8 * ki + t4 + 4) * VP + g;
            #pragma unroll
            for (int ni = 0; ni < 8; ++ni) {
                mma_tf32(o[ni], a0, a1, a2, a3, v0[8 * ni], v1[8 * ni]);
            }
        }

        cm0 = nm0; cm1 = nm1; cm2 = nm2; cm3 = nm3;
    }

    float inv0 = (l0 > 0.f) ? (1.f / l0) : 0.f;
    float inv1 = (l1 > 0.f) ? (1.f / l1) : 0.f;
    #pragma unroll
    for (int ni = 0; ni < 8; ++ni) {
        int col = hb + 8 * ni + 2 * t4;
        *(float2*)(O + (size_t)(row0 + g)     * EMB + col) =
            make_float2(o[ni][0] * inv0, o[ni][1] * inv0);
        *(float2*)(O + (size_t)(row0 + g + 8) * EMB + col) =
            make_float2(o[ni][2] * inv1, o[ni][3] * inv1);
    }
}

// ---------------------------------------------------------------------------
extern "C" void kernel_launch(void* const* d_in, const int* in_sizes, int n_in,
                              void* d_out, int out_size)
{
    const float* q    = (const float*)d_in[0];
    const float* k    = (const float*)d_in[1];
    const float* v    = (const float*)d_in[2];
    const int*   mask = (const int*)d_in[3];
    const float* Wq   = (const float*)d_in[4];
    const float* Wk   = (const float*)d_in[5];
    const float* Wv   = (const float*)d_in[6];
    const float* Wo   = (const float*)d_in[7];
    float*       out  = (float*)d_out;

    float *gQ, *gK, *gV, *gA;
    uint32_t* gMp;
    cudaGetSymbolAddress((void**)&gQ, g_Q);
    cudaGetSymbolAddress((void**)&gK, g_K);
    cudaGetSymbolAddress((void**)&gV, g_V);
    cudaGetSymbolAddress((void**)&gA, g_A);
    cudaGetSymbolAddress((void**)&gMp, g_Mp);

    cudaFuncSetAttribute(attn_mma_kernel,
                         cudaFuncAttributeMaxDynamicSharedMemorySize, ATTN_SMEM);

    maskpack_kernel<<<2048, 256>>>(mask, gMp);

    dim3 ggrid(EMB / 128, Lq / 64);    // (8, 32) = 256 CTAs

    gemm_mma_kernel<<<ggrid, 256>>>(q, Wq, gQ);
    gemm_mma_kernel<<<ggrid, 256>>>(k, Wk, gK);
    gemm_mma_kernel<<<ggrid, 256>>>(v, Wv, gV);

    dim3 agrid(Lq / 128, NHEAD);       // (16, 16)
    attn_mma_kernel<<<agrid, 256, ATTN_SMEM>>>(gQ, gK, gV, gMp, gA);

    gemm_mma_kernel<<<ggrid, 256>>>(gA, Wo, out);
}

// round 10
// speedup vs baseline: 1.5020x; 1.1007x over previous
#include <cuda_runtime.h>
#include <cuda_bf16.h>
#include <stdint.h>

#define Lq     2048
#define EMB    1024
#define NHEAD  16
#define HD     64
#define NT     (Lq / 64)                       // key tiles
#define MP_WORDS (NHEAD * Lq * (Lq / 32))      // packed mask words

// Scratch (allocation-free rule: device globals)
__device__ float    g_Q[Lq * EMB];
__device__ float    g_K[Lq * EMB];
__device__ float    g_V[Lq * EMB];
__device__ float    g_A[Lq * EMB];
__device__ uint32_t g_Mp[MP_WORDS];            // bit-packed mask (8 MB)

__device__ __forceinline__ float to_tf32(float x) {
    float r; asm("cvt.rna.tf32.f32 %0, %1;" : "=f"(r) : "f"(x)); return r;
}
__device__ __forceinline__ uint32_t smem_u32(const void* p) {
    uint32_t a;
    asm("{ .reg .u64 t; cvta.to.shared.u64 t, %1; cvt.u32.u64 %0, t; }" : "=r"(a) : "l"(p));
    return a;
}
// pack two floats -> bf16x2 (x0 low half, x1 high half)
__device__ __forceinline__ uint32_t cvt2bf(float x0, float x1) {
    uint32_t r;
    asm("cvt.rn.bf16x2.f32 %0, %1, %2;" : "=r"(r) : "f"(x1), "f"(x0));
    return r;
}
__device__ __forceinline__ float bf_lowf(uint32_t h)  { return __uint_as_float(h << 16); }
__device__ __forceinline__ float bf_highf(uint32_t h) { return __uint_as_float(h & 0xffff0000u); }

// m16n8k8 tf32 HMMA (attention PV path)
__device__ __forceinline__ void mma_tf32(float d[4], const float a0, const float a1,
                                         const float a2, const float a3,
                                         const float b0, const float b1) {
    asm volatile(
        "mma.sync.aligned.m16n8k8.row.col.f32.tf32.tf32.f32 "
        "{%0,%1,%2,%3}, {%4,%5,%6,%7}, {%8,%9}, {%0,%1,%2,%3};\n"
        : "+f"(d[0]), "+f"(d[1]), "+f"(d[2]), "+f"(d[3])
        : "r"(__float_as_uint(a0)), "r"(__float_as_uint(a1)),
          "r"(__float_as_uint(a2)), "r"(__float_as_uint(a3)),
          "r"(__float_as_uint(b0)), "r"(__float_as_uint(b1)));
}

// m16n8k16 bf16 HMMA
__device__ __forceinline__ void mma_bf16(float d[4], const uint32_t a[4],
                                         const uint32_t b0, const uint32_t b1) {
    asm volatile(
        "mma.sync.aligned.m16n8k16.row.col.f32.bf16.bf16.f32 "
        "{%0,%1,%2,%3}, {%4,%5,%6,%7}, {%8,%9}, {%0,%1,%2,%3};\n"
        : "+f"(d[0]), "+f"(d[1]), "+f"(d[2]), "+f"(d[3])
        : "r"(a[0]), "r"(a[1]), "r"(a[2]), "r"(a[3]), "r"(b0), "r"(b1));
}

__device__ __forceinline__ void ldsm4(uint32_t r[4], uint32_t addr) {
    asm volatile("ldmatrix.sync.aligned.m8n8.x4.shared.b16 {%0,%1,%2,%3}, [%4];"
                 : "=r"(r[0]), "=r"(r[1]), "=r"(r[2]), "=r"(r[3]) : "r"(addr));
}

// ===========================================================================
// Mask bit-pack: int32[H*L*L] -> u32 bits (ballot).
// ===========================================================================
__global__ __launch_bounds__(256)
void maskpack_kernel(const int* __restrict__ mask, uint32_t* __restrict__ mp)
{
    const int lane = threadIdx.x & 31;
    const int wgid = (blockIdx.x * blockDim.x + threadIdx.x) >> 5;
    const int nw   = (gridDim.x * blockDim.x) >> 5;
    for (int w = wgid; w < MP_WORDS; w += nw) {
        int v = mask[(size_t)w * 32 + lane];
        uint32_t bits = __ballot_sync(0xffffffffu, v != 0);
        if (lane == 0) mp[w] = bits;
    }
}

// ===========================================================================
// bf16 3xsplit NT GEMM via m16n8k16 + ldmatrix (unchanged from R9; 60us).
// ===========================================================================
__global__ __launch_bounds__(256, 2)
void gemm_mma_kernel(const float* __restrict__ A, const float* __restrict__ B,
                     float* __restrict__ C)
{
    __shared__ uint32_t Ah[64][12],  Al[64][12];
    __shared__ uint32_t Bh[128][12], Bl[128][12];

    const int tid  = threadIdx.x;
    const int lane = tid & 31;
    const int wid  = tid >> 5;
    const int g    = lane >> 2;
    const int t4   = lane & 3;
    const int wm   = (wid & 1) * 32;
    const int wn   = (wid >> 1) * 32;

    const int bm = blockIdx.y * 64;
    const int bn = blockIdx.x * 128;

    const int ar = tid >> 2;
    const int br = tid >> 1;
    const float* ap = A + (size_t)(bm + ar) * EMB + (tid & 3) * 4;
    const float* bp = B + (size_t)(bn + br) * EMB + (tid & 1) * 8;

    const uint32_t sAh = smem_u32(Ah), sAl = smem_u32(Al);
    const uint32_t sBh = smem_u32(Bh), sBl = smem_u32(Bl);
    const int arow = lane & 15, akoff = (lane >> 4) * 16;
    const int brow = (lane & 7) + ((lane >> 4) << 3);
    const int bkoff = ((lane >> 3) & 1) * 16;
    uint32_t aAh[2], aAl[2], aBh[2], aBl[2];
    #pragma unroll
    for (int mi = 0; mi < 2; ++mi) {
        aAh[mi] = sAh + (wm + 16 * mi + arow) * 48 + akoff;
        aAl[mi] = sAl + (wm + 16 * mi + arow) * 48 + akoff;
    }
    #pragma unroll
    for (int p = 0; p < 2; ++p) {
        aBh[p] = sBh + (wn + 16 * p + brow) * 48 + bkoff;
        aBl[p] = sBl + (wn + 16 * p + brow) * 48 + bkoff;
    }

    float d[2][4][4];
    #pragma unroll
    for (int i = 0; i < 2; ++i)
        #pragma unroll
        for (int j = 0; j < 4; ++j)
            #pragma unroll
            for (int r = 0; r < 4; ++r) d[i][j][r] = 0.f;

    float4 pa  = *(const float4*)ap;
    float4 pb0 = *(const float4*)bp;
    float4 pb1 = *(const float4*)(bp + 4);

    #pragma unroll 1
    for (int c = 0; c < EMB / 16; ++c) {
        __syncthreads();
        {
            uint32_t h0 = cvt2bf(pa.x, pa.y);
            uint32_t h1 = cvt2bf(pa.z, pa.w);
            uint32_t l0 = cvt2bf(pa.x - bf_lowf(h0), pa.y - bf_highf(h0));
            uint32_t l1 = cvt2bf(pa.z - bf_lowf(h1), pa.w - bf_highf(h1));
            *(uint2*)&Ah[ar][(tid & 3) * 2] = make_uint2(h0, h1);
            *(uint2*)&Al[ar][(tid & 3) * 2] = make_uint2(l0, l1);

            uint32_t bh0 = cvt2bf(pb0.x, pb0.y), bh1 = cvt2bf(pb0.z, pb0.w);
            uint32_t bh2 = cvt2bf(pb1.x, pb1.y), bh3 = cvt2bf(pb1.z, pb1.w);
            uint32_t bl0 = cvt2bf(pb0.x - bf_lowf(bh0), pb0.y - bf_highf(bh0));
            uint32_t bl1 = cvt2bf(pb0.z - bf_lowf(bh1), pb0.w - bf_highf(bh1));
            uint32_t bl2 = cvt2bf(pb1.x - bf_lowf(bh2), pb1.y - bf_highf(bh2));
            uint32_t bl3 = cvt2bf(pb1.z - bf_lowf(bh3), pb1.w - bf_highf(bh3));
            *(uint4*)&Bh[br][(tid & 1) * 4] = make_uint4(bh0, bh1, bh2, bh3);
            *(uint4*)&Bl[br][(tid & 1) * 4] = make_uint4(bl0, bl1, bl2, bl3);
        }
        if (c + 1 < EMB / 16) {
            pa  = *(const float4*)(ap + (c + 1) * 16);
            pb0 = *(const float4*)(bp + (c + 1) * 16);
            pb1 = *(const float4*)(bp + (c + 1) * 16 + 4);
        }
        __syncthreads();

        uint32_t fah[2][4], fal[2][4], fbh[2][4], fbl[2][4];
        #pragma unroll
        for (int mi = 0; mi < 2; ++mi) { ldsm4(fah[mi], aAh[mi]); ldsm4(fal[mi], aAl[mi]); }
        #pragma unroll
        for (int p = 0; p < 2; ++p)    { ldsm4(fbh[p], aBh[p]);   ldsm4(fbl[p], aBl[p]); }

        #pragma unroll
        for (int mi = 0; mi < 2; ++mi) {
            #pragma unroll
            for (int ni = 0; ni < 4; ++ni) {
                const int p = ni >> 1, q = (ni & 1) * 2;
                uint32_t b0h = fbh[p][q], b1h = fbh[p][q + 1];
                uint32_t b0l = fbl[p][q], b1l = fbl[p][q + 1];
                mma_bf16(d[mi][ni], fah[mi], b0h, b1h);
                mma_bf16(d[mi][ni], fah[mi], b0l, b1l);
                mma_bf16(d[mi][ni], fal[mi], b0h, b1h);
            }
        }
    }

    #pragma unroll
    for (int mi = 0; mi < 2; ++mi) {
        int m = bm + wm + mi * 16 + g;
        #pragma unroll
        for (int ni = 0; ni < 4; ++ni) {
            int n = bn + wn + ni * 8 + 2 * t4;
            *(float2*)(C + (size_t)m * EMB + n)       = make_float2(d[mi][ni][0], d[mi][ni][1]);
            *(float2*)(C + (size_t)(m + 8) * EMB + n) = make_float2(d[mi][ni][2], d[mi][ni][3]);
        }
    }
}

// ===========================================================================
// Tensor-core flash attention v4:
//  - S = QK^T: bf16 2-split (hi/lo) via m16n8k16 + ldmatrix (GEMM-validated
//    fragment addressing). 96 MMA + 32 LDSM per warp-tile (was 192 MMA +
//    256 scalar LDS).
//  - K staged as bf16 hi/lo planes, row stride 144B (ldmatrix conflict-free).
//  - PV: tf32 k8 path unchanged (identical rounding to R9).
//  - 72KB smem double-buffered, occupancy 2 -> single wave, cross-CTA overlap.
// ===========================================================================
#define KROWB  144
#define KPLANE (64 * KROWB)          // 9216
#define KBUFB  (2 * KPLANE)          // 18432 (hi+lo)
#define VROWF  72
#define VBUFB  (64 * VROWF * 4)      // 18432
#define OFF_V  (2 * KBUFB)           // 36864
#define ATTN_SMEM (2 * KBUFB + 2 * VBUFB)   // 73728

__global__ __launch_bounds__(256, 2)
void attn_mma_kernel(const float* __restrict__ Q, const float* __restrict__ Kg,
                     const float* __restrict__ Vg, const uint32_t* __restrict__ Mp,
                     float* __restrict__ O)
{
    extern __shared__ char smem[];
    const uint32_t sbase = smem_u32(smem);

    const int tid  = threadIdx.x;
    const int lane = tid & 31;
    const int wid  = tid >> 5;
    const int g    = lane >> 2;
    const int t4   = lane & 3;
    const int h    = blockIdx.y;
    const int qb   = blockIdx.x;
    const int hb   = h * HD;
    const int row0 = qb * 128 + wid * 16;

    // ---- Q fragments: bf16 hi/lo, m16n8k16 A layout, resident in regs ----
    uint32_t qfh[4][4], qfl[4][4];
    #pragma unroll
    for (int s = 0; s < 4; ++s) {
        const float* qr0 = Q + (size_t)(row0 + g)     * EMB + hb + 16 * s + 2 * t4;
        const float* qr1 = Q + (size_t)(row0 + g + 8) * EMB + hb + 16 * s + 2 * t4;
        float x0 = qr0[0] * 0.125f, x1 = qr0[1] * 0.125f;
        float y0 = qr1[0] * 0.125f, y1 = qr1[1] * 0.125f;
        float z0 = qr0[8] * 0.125f, z1 = qr0[9] * 0.125f;
        float w0 = qr1[8] * 0.125f, w1 = qr1[9] * 0.125f;
        qfh[s][0] = cvt2bf(x0, x1);
        qfl[s][0] = cvt2bf(x0 - bf_lowf(qfh[s][0]), x1 - bf_highf(qfh[s][0]));
        qfh[s][1] = cvt2bf(y0, y1);
        qfl[s][1] = cvt2bf(y0 - bf_lowf(qfh[s][1]), y1 - bf_highf(qfh[s][1]));
        qfh[s][2] = cvt2bf(z0, z1);
        qfl[s][2] = cvt2bf(z0 - bf_lowf(qfh[s][2]), z1 - bf_highf(qfh[s][2]));
        qfh[s][3] = cvt2bf(w0, w1);
        qfl[s][3] = cvt2bf(w0 - bf_lowf(qfh[s][3]), w1 - bf_highf(qfh[s][3]));
    }

    float o[8][4];
    #pragma unroll
    for (int ni = 0; ni < 8; ++ni)
        #pragma unroll
        for (int r = 0; r < 4; ++r) o[ni][r] = 0.f;
    float m0 = -1.0e30f, m1 = -1.0e30f;
    float l0 = 0.f, l1 = 0.f;

    // staging coordinates
    const int key = tid >> 2;          // key row this thread stages (0..63)
    const int qq  = tid & 3;           // 16-dim segment
    const float* kbase = Kg + (size_t)key * EMB + hb + qq * 16;
    const float* vbase = Vg + (size_t)key * EMB + hb + qq * 16;

    // ldmatrix read addresses (per warp)
    const int brow  = (lane & 7) + ((lane >> 4) << 3);
    const int bkoff = ((lane >> 3) & 1) * 16;
    const uint32_t kaddr0 = sbase + brow * KROWB + bkoff;

    const int rbase = wid * 16 + g;
    const uint32_t* mp0 = Mp + ((size_t)h * Lq + qb * 128 + rbase) * (Lq / 32);
    const uint32_t* mp1 = mp0 + 8 * (Lq / 32);

    // -------- staging helper (expanded inline twice) --------
    #define STAGE_TILE(T, BUF) do {                                              \
        const float* ksrc = kbase + (size_t)(T) * 64 * EMB;                      \
        float4 x0 = *(const float4*)(ksrc);                                      \
        float4 x1 = *(const float4*)(ksrc + 4);                                  \
        float4 x2 = *(const float4*)(ksrc + 8);                                  \
        float4 x3 = *(const float4*)(ksrc + 12);                                 \
        uint32_t h0 = cvt2bf(x0.x, x0.y), h1 = cvt2bf(x0.z, x0.w);               \
        uint32_t h2 = cvt2bf(x1.x, x1.y), h3 = cvt2bf(x1.z, x1.w);               \
        uint32_t h4 = cvt2bf(x2.x, x2.y), h5 = cvt2bf(x2.z, x2.w);               \
        uint32_t h6 = cvt2bf(x3.x, x3.y), h7 = cvt2bf(x3.z, x3.w);               \
        uint32_t l0_ = cvt2bf(x0.x - bf_lowf(h0), x0.y - bf_highf(h0));          \
        uint32_t l1_ = cvt2bf(x0.z - bf_lowf(h1), x0.w - bf_highf(h1));          \
        uint32_t l2_ = cvt2bf(x1.x - bf_lowf(h2), x1.y - bf_highf(h2));          \
        uint32_t l3_ = cvt2bf(x1.z - bf_lowf(h3), x1.w - bf_highf(h3));          \
        uint32_t l4_ = cvt2bf(x2.x - bf_lowf(h4), x2.y - bf_highf(h4));          \
        uint32_t l5_ = cvt2bf(x2.z - bf_lowf(h5), x2.w - bf_highf(h5));          \
        uint32_t l6_ = cvt2bf(x3.x - bf_lowf(h6), x3.y - bf_highf(h6));          \
        uint32_t l7_ = cvt2bf(x3.z - bf_lowf(h7), x3.w - bf_highf(h7));          \
        char* kh = smem + (BUF) * KBUFB + key * KROWB + qq * 32;                 \
        *(uint4*)(kh)              = make_uint4(h0, h1, h2, h3);                 \
        *(uint4*)(kh + 16)         = make_uint4(h4, h5, h6, h7);                 \
        *(uint4*)(kh + KPLANE)     = make_uint4(l0_, l1_, l2_, l3_);             \
        *(uint4*)(kh + KPLANE + 16)= make_uint4(l4_, l5_, l6_, l7_);             \
        const float* vsrc = vbase + (size_t)(T) * 64 * EMB;                      \
        float4 v0 = *(const float4*)(vsrc);                                      \
        float4 v1 = *(const float4*)(vsrc + 4);                                  \
        float4 v2 = *(const float4*)(vsrc + 8);                                  \
        float4 v3 = *(const float4*)(vsrc + 12);                                 \
        float* vd = (float*)(smem + OFF_V + (BUF) * VBUFB) + key * VROWF + qq * 16; \
        *(float4*)(vd)      = make_float4(to_tf32(v0.x), to_tf32(v0.y), to_tf32(v0.z), to_tf32(v0.w)); \
        *(float4*)(vd + 4)  = make_float4(to_tf32(v1.x), to_tf32(v1.y), to_tf32(v1.z), to_tf32(v1.w)); \
        *(float4*)(vd + 8)  = make_float4(to_tf32(v2.x), to_tf32(v2.y), to_tf32(v2.z), to_tf32(v2.w)); \
        *(float4*)(vd + 12) = make_float4(to_tf32(v3.x), to_tf32(v3.y), to_tf32(v3.z), to_tf32(v3.w)); \
    } while (0)

    STAGE_TILE(0, 0);
    __syncthreads();

    #pragma unroll 1
    for (int kt = 0; kt < NT; ++kt) {
        const int b = kt & 1;

        // masks for THIS tile (used after S-phase; latency hidden by MMAs)
        uint32_t cm0 = mp0[kt * 2],     cm1 = mp0[kt * 2 + 1];
        uint32_t cm2 = mp1[kt * 2],     cm3 = mp1[kt * 2 + 1];

        // stage NEXT tile into the other buffer (overlaps with compute below)
        if (kt + 1 < NT) STAGE_TILE(kt + 1, b ^ 1);

        // ================= S = Q K^T (bf16 2-split via ldmatrix) ===========
        float s[8][4];
        #pragma unroll
        for (int ni = 0; ni < 8; ++ni)
            #pragma unroll
            for (int r = 0; r < 4; ++r) s[ni][r] = 0.f;

        const uint32_t ka = kaddr0 + b * KBUFB;
        #pragma unroll
        for (int sstep = 0; sstep < 4; ++sstep) {
            #pragma unroll
            for (int p = 0; p < 4; ++p) {
                uint32_t fh[4], fl[4];
                ldsm4(fh, ka + p * 16 * KROWB + sstep * 32);
                ldsm4(fl, ka + p * 16 * KROWB + sstep * 32 + KPLANE);
                #pragma unroll
                for (int q = 0; q < 2; ++q) {
                    const int ni = 2 * p + q;
                    mma_bf16(s[ni], qfh[sstep], fh[2 * q], fh[2 * q + 1]);
                    mma_bf16(s[ni], qfh[sstep], fl[2 * q], fl[2 * q + 1]);
                    mma_bf16(s[ni], qfl[sstep], fh[2 * q], fh[2 * q + 1]);
                }
            }
        }

        // ================= masked online softmax ===========================
        float tm0 = -1.0e30f, tm1 = -1.0e30f;
        #pragma unroll
        for (int ni = 0; ni < 8; ++ni) {
            uint32_t wr0 = (ni < 4) ? cm0 : cm1;
            uint32_t wr1 = (ni < 4) ? cm2 : cm3;
            int b2 = 8 * (ni & 3) + 2 * t4;
            tm0 = fmaxf(tm0, ((wr0 >> b2) & 1u)       ? -1.0e30f : s[ni][0]);
            tm0 = fmaxf(tm0, ((wr0 >> (b2 + 1)) & 1u) ? -1.0e30f : s[ni][1]);
            tm1 = fmaxf(tm1, ((wr1 >> b2) & 1u)       ? -1.0e30f : s[ni][2]);
            tm1 = fmaxf(tm1, ((wr1 >> (b2 + 1)) & 1u) ? -1.0e30f : s[ni][3]);
        }
        tm0 = fmaxf(tm0, __shfl_xor_sync(0xffffffffu, tm0, 1));
        tm0 = fmaxf(tm0, __shfl_xor_sync(0xffffffffu, tm0, 2));
        tm1 = fmaxf(tm1, __shfl_xor_sync(0xffffffffu, tm1, 1));
        tm1 = fmaxf(tm1, __shfl_xor_sync(0xffffffffu, tm1, 2));

        float mn0 = fmaxf(m0, tm0), mn1 = fmaxf(m1, tm1);
        float c0 = __expf(m0 - mn0), c1 = __expf(m1 - mn1);
        m0 = mn0; m1 = mn1;

        float rs0 = 0.f, rs1 = 0.f;
        #pragma unroll
        for (int ni = 0; ni < 8; ++ni) {
            uint32_t wr0 = (ni < 4) ? cm0 : cm1;
            uint32_t wr1 = (ni < 4) ? cm2 : cm3;
            int b2 = 8 * (ni & 3) + 2 * t4;
            float p0 = ((wr0 >> b2) & 1u)       ? 0.f : __expf(s[ni][0] - mn0);
            float p1 = ((wr0 >> (b2 + 1)) & 1u) ? 0.f : __expf(s[ni][1] - mn0);
            float p2 = ((wr1 >> b2) & 1u)       ? 0.f : __expf(s[ni][2] - mn1);
            float p3 = ((wr1 >> (b2 + 1)) & 1u) ? 0.f : __expf(s[ni][3] - mn1);
            s[ni][0] = p0; s[ni][1] = p1; s[ni][2] = p2; s[ni][3] = p3;
            rs0 += p0 + p1; rs1 += p2 + p3;
        }
        rs0 += __shfl_xor_sync(0xffffffffu, rs0, 1);
        rs0 += __shfl_xor_sync(0xffffffffu, rs0, 2);
        rs1 += __shfl_xor_sync(0xffffffffu, rs1, 1);
        rs1 += __shfl_xor_sync(0xffffffffu, rs1, 2);
        l0 = l0 * c0 + rs0;
        l1 = l1 * c1 + rs1;

        #pragma unroll
        for (int ni = 0; ni < 8; ++ni) {
            o[ni][0] *= c0; o[ni][1] *= c0;
            o[ni][2] *= c1; o[ni][3] *= c1;
        }

        // ================= O += P V (tf32, unchanged) ======================
        const float* Vsb = (const float*)(smem + OFF_V + b * VBUFB);
        const int srcA = g * 4 + (t4 >> 1);
        const int srcB = srcA + 2;
        const int par  = t4 & 1;
        #pragma unroll
        for (int ki = 0; ki < 8; ++ki) {
            float e0 = __shfl_sync(0xffffffffu, s[ki][0], srcA);
            float o0 = __shfl_sync(0xffffffffu, s[ki][1], srcA);
            float e2 = __shfl_sync(0xffffffffu, s[ki][0], srcB);
            float o2 = __shfl_sync(0xffffffffu, s[ki][1], srcB);
            float e1 = __shfl_sync(0xffffffffu, s[ki][2], srcA);
            float o1 = __shfl_sync(0xffffffffu, s[ki][3], srcA);
            float e3 = __shfl_sync(0xffffffffu, s[ki][2], srcB);
            float o3 = __shfl_sync(0xffffffffu, s[ki][3], srcB);
            float a0 = to_tf32(par ? o0 : e0);
            float a1 = to_tf32(par ? o1 : e1);
            float a2 = to_tf32(par ? o2 : e2);
            float a3 = to_tf32(par ? o3 : e3);
            const float* v0 = Vsb + (8 * ki + t4) * VROWF + g;
            const float* v1 = Vsb + (8 * ki + t4 + 4) * VROWF + g;
            #pragma unroll
            for (int ni = 0; ni < 8; ++ni) {
                mma_tf32(o[ni], a0, a1, a2, a3, v0[8 * ni], v1[8 * ni]);
            }
        }

        __syncthreads();
    }

    // ================= epilogue =================
    float inv0 = (l0 > 0.f) ? (1.f / l0) : 0.f;
    float inv1 = (l1 > 0.f) ? (1.f / l1) : 0.f;
    #pragma unroll
    for (int ni = 0; ni < 8; ++ni) {
        int col = hb + 8 * ni + 2 * t4;
        *(float2*)(O + (size_t)(row0 + g)     * EMB + col) =
            make_float2(o[ni][0] * inv0, o[ni][1] * inv0);
        *(float2*)(O + (size_t)(row0 + g + 8) * EMB + col) =
            make_float2(o[ni][2] * inv1, o[ni][3] * inv1);
    }
}

// ---------------------------------------------------------------------------
extern "C" void kernel_launch(void* const* d_in, const int* in_sizes, int n_in,
                              void* d_out, int out_size)
{
    const float* q    = (const float*)d_in[0];
    const float* k    = (const float*)d_in[1];
    const float* v    = (const float*)d_in[2];
    const int*   mask = (const int*)d_in[3];
    const float* Wq   = (const float*)d_in[4];
    const float* Wk   = (const float*)d_in[5];
    const float* Wv   = (const float*)d_in[6];
    const float* Wo   = (const float*)d_in[7];
    float*       out  = (float*)d_out;

    float *gQ, *gK, *gV, *gA;
    uint32_t* gMp;
    cudaGetSymbolAddress((void**)&gQ, g_Q);
    cudaGetSymbolAddress((void**)&gK, g_K);
    cudaGetSymbolAddress((void**)&gV, g_V);
    cudaGetSymbolAddress((void**)&gA, g_A);
    cudaGetSymbolAddress((void**)&gMp, g_Mp);

    cudaFuncSetAttribute(attn_mma_kernel,
                         cudaFuncAttributeMaxDynamicSharedMemorySize, ATTN_SMEM);

    maskpack_kernel<<<2048, 256>>>(mask, gMp);

    dim3 ggrid(EMB / 128, Lq / 64);    // (8, 32) = 256 CTAs

    gemm_mma_kernel<<<ggrid, 256>>>(q, Wq, gQ);
    gemm_mma_kernel<<<ggrid, 256>>>(k, Wk, gK);
    gemm_mma_kernel<<<ggrid, 256>>>(v, Wv, gV);

    dim3 agrid(Lq / 128, NHEAD);       // (16, 16)
    attn_mma_kernel<<<agrid, 256, ATTN_SMEM>>>(gQ, gK, gV, gMp, gA);

    gemm_mma_kernel<<<ggrid, 256>>>(gA, Wo, out);
}

// round 11
// speedup vs baseline: 1.5072x; 1.0035x over previous
#include <cuda_runtime.h>
#include <cuda_bf16.h>
#include <stdint.h>

#define Lq     2048
#define EMB    1024
#define NHEAD  16
#define HD     64
#define NT     (Lq / 64)                       // key tiles
#define MP_WORDS (NHEAD * Lq * (Lq / 32))      // packed mask words

// Scratch (allocation-free rule: device globals)
__device__ float    g_Q[Lq * EMB];
__device__ float    g_K[Lq * EMB];
__device__ float    g_V[Lq * EMB];
__device__ float    g_A[Lq * EMB];
__device__ uint32_t g_Mp[MP_WORDS];            // bit-packed mask (8 MB)

__device__ __forceinline__ uint32_t smem_u32(const void* p) {
    uint32_t a;
    asm("{ .reg .u64 t; cvta.to.shared.u64 t, %1; cvt.u32.u64 %0, t; }" : "=r"(a) : "l"(p));
    return a;
}
// pack two floats -> bf16x2 (x0 low half, x1 high half)
__device__ __forceinline__ uint32_t cvt2bf(float x0, float x1) {
    uint32_t r;
    asm("cvt.rn.bf16x2.f32 %0, %1, %2;" : "=r"(r) : "f"(x1), "f"(x0));
    return r;
}
__device__ __forceinline__ float bf_lowf(uint32_t h)  { return __uint_as_float(h << 16); }
__device__ __forceinline__ float bf_highf(uint32_t h) { return __uint_as_float(h & 0xffff0000u); }

// m16n8k16 bf16 HMMA
__device__ __forceinline__ void mma_bf16(float d[4], const uint32_t a[4],
                                         const uint32_t b0, const uint32_t b1) {
    asm volatile(
        "mma.sync.aligned.m16n8k16.row.col.f32.bf16.bf16.f32 "
        "{%0,%1,%2,%3}, {%4,%5,%6,%7}, {%8,%9}, {%0,%1,%2,%3};\n"
        : "+f"(d[0]), "+f"(d[1]), "+f"(d[2]), "+f"(d[3])
        : "r"(a[0]), "r"(a[1]), "r"(a[2]), "r"(a[3]), "r"(b0), "r"(b1));
}

__device__ __forceinline__ void ldsm4(uint32_t r[4], uint32_t addr) {
    asm volatile("ldmatrix.sync.aligned.m8n8.x4.shared.b16 {%0,%1,%2,%3}, [%4];"
                 : "=r"(r[0]), "=r"(r[1]), "=r"(r[2]), "=r"(r[3]) : "r"(addr));
}
__device__ __forceinline__ void ldsm4t(uint32_t r[4], uint32_t addr) {
    asm volatile("ldmatrix.sync.aligned.m8n8.x4.trans.shared.b16 {%0,%1,%2,%3}, [%4];"
                 : "=r"(r[0]), "=r"(r[1]), "=r"(r[2]), "=r"(r[3]) : "r"(addr));
}

// ===========================================================================
// Mask bit-pack: int32[H*L*L] -> u32 bits (ballot).
// ===========================================================================
__global__ __launch_bounds__(256)
void maskpack_kernel(const int* __restrict__ mask, uint32_t* __restrict__ mp)
{
    const int lane = threadIdx.x & 31;
    const int wgid = (blockIdx.x * blockDim.x + threadIdx.x) >> 5;
    const int nw   = (gridDim.x * blockDim.x) >> 5;
    for (int w = wgid; w < MP_WORDS; w += nw) {
        int v = mask[(size_t)w * 32 + lane];
        uint32_t bits = __ballot_sync(0xffffffffu, v != 0);
        if (lane == 0) mp[w] = bits;
    }
}

// ===========================================================================
// bf16 3xsplit NT GEMM via m16n8k16 + ldmatrix. BK=32 (32 iterations).
// CTA tile 64x128, grid (8,32)=256 CTAs. 8 warps (2m x 4n), warp 32x32.
// Smem planes row stride 80B (64B data + 16B pad; ldmatrix conflict-free).
// ===========================================================================
__global__ __launch_bounds__(256, 2)
void gemm_mma_kernel(const float* __restrict__ A, const float* __restrict__ B,
                     float* __restrict__ C)
{
    __shared__ uint32_t Ah[64][20],  Al[64][20];    // 64 rows x 80B
    __shared__ uint32_t Bh[128][20], Bl[128][20];   // 128 rows x 80B

    const int tid  = threadIdx.x;
    const int lane = tid & 31;
    const int wid  = tid >> 5;
    const int g    = lane >> 2;
    const int t4   = lane & 3;
    const int wm   = (wid & 1) * 32;
    const int wn   = (wid >> 1) * 32;

    const int bm = blockIdx.y * 64;
    const int bn = blockIdx.x * 128;

    // loader coords: A 64x32 (4 thr/row, 2 float4 each); B 128x32 (2 thr/row, 4 float4)
    const int ar = tid >> 2, aw = tid & 3;        // A row, float4 slot
    const int br = tid >> 1, bw = tid & 1;        // B row, half
    const float* ap = A + (size_t)(bm + ar) * EMB + aw * 4;
    const float* bp = B + (size_t)(bn + br) * EMB + bw * 16;

    const uint32_t sAh = smem_u32(Ah), sAl = smem_u32(Al);
    const uint32_t sBh = smem_u32(Bh), sBl = smem_u32(Bl);
    const int arow = lane & 15, akoff = (lane >> 4) * 16;
    const int brow = (lane & 7) + ((lane >> 4) << 3);
    const int bkoff = ((lane >> 3) & 1) * 16;
    uint32_t aAh[2], aAl[2], aBh[2], aBl[2];
    #pragma unroll
    for (int mi = 0; mi < 2; ++mi) {
        aAh[mi] = sAh + (wm + 16 * mi + arow) * 80 + akoff;
        aAl[mi] = sAl + (wm + 16 * mi + arow) * 80 + akoff;
    }
    #pragma unroll
    for (int p = 0; p < 2; ++p) {
        aBh[p] = sBh + (wn + 16 * p + brow) * 80 + bkoff;
        aBl[p] = sBl + (wn + 16 * p + brow) * 80 + bkoff;
    }

    float d[2][4][4];
    #pragma unroll
    for (int i = 0; i < 2; ++i)
        #pragma unroll
        for (int j = 0; j < 4; ++j)
            #pragma unroll
            for (int r = 0; r < 4; ++r) d[i][j][r] = 0.f;

    float4 pa0 = *(const float4*)(ap);
    float4 pa1 = *(const float4*)(ap + 16);
    float4 pb0 = *(const float4*)(bp);
    float4 pb1 = *(const float4*)(bp + 4);
    float4 pb2 = *(const float4*)(bp + 8);
    float4 pb3 = *(const float4*)(bp + 12);

    #pragma unroll 1
    for (int c = 0; c < EMB / 32; ++c) {
        __syncthreads();
        // ---- split & store chunk (A: cols aw*4 and aw*4+16; B: 16 cols) ----
        {
            uint32_t h0 = cvt2bf(pa0.x, pa0.y), h1 = cvt2bf(pa0.z, pa0.w);
            uint32_t l0 = cvt2bf(pa0.x - bf_lowf(h0), pa0.y - bf_highf(h0));
            uint32_t l1 = cvt2bf(pa0.z - bf_lowf(h1), pa0.w - bf_highf(h1));
            *(uint2*)&Ah[ar][aw * 2] = make_uint2(h0, h1);
            *(uint2*)&Al[ar][aw * 2] = make_uint2(l0, l1);
            h0 = cvt2bf(pa1.x, pa1.y); h1 = cvt2bf(pa1.z, pa1.w);
            l0 = cvt2bf(pa1.x - bf_lowf(h0), pa1.y - bf_highf(h0));
            l1 = cvt2bf(pa1.z - bf_lowf(h1), pa1.w - bf_highf(h1));
            *(uint2*)&Ah[ar][aw * 2 + 8] = make_uint2(h0, h1);
            *(uint2*)&Al[ar][aw * 2 + 8] = make_uint2(l0, l1);

            uint32_t bh0 = cvt2bf(pb0.x, pb0.y), bh1 = cvt2bf(pb0.z, pb0.w);
            uint32_t bh2 = cvt2bf(pb1.x, pb1.y), bh3 = cvt2bf(pb1.z, pb1.w);
            uint32_t bh4 = cvt2bf(pb2.x, pb2.y), bh5 = cvt2bf(pb2.z, pb2.w);
            uint32_t bh6 = cvt2bf(pb3.x, pb3.y), bh7 = cvt2bf(pb3.z, pb3.w);
            uint32_t bl0 = cvt2bf(pb0.x - bf_lowf(bh0), pb0.y - bf_highf(bh0));
            uint32_t bl1 = cvt2bf(pb0.z - bf_lowf(bh1), pb0.w - bf_highf(bh1));
            uint32_t bl2 = cvt2bf(pb1.x - bf_lowf(bh2), pb1.y - bf_highf(bh2));
            uint32_t bl3 = cvt2bf(pb1.z - bf_lowf(bh3), pb1.w - bf_highf(bh3));
            uint32_t bl4 = cvt2bf(pb2.x - bf_lowf(bh4), pb2.y - bf_highf(bh4));
            uint32_t bl5 = cvt2bf(pb2.z - bf_lowf(bh5), pb2.w - bf_highf(bh5));
            uint32_t bl6 = cvt2bf(pb3.x - bf_lowf(bh6), pb3.y - bf_highf(bh6));
            uint32_t bl7 = cvt2bf(pb3.z - bf_lowf(bh7), pb3.w - bf_highf(bh7));
            *(uint4*)&Bh[br][bw * 8]     = make_uint4(bh0, bh1, bh2, bh3);
            *(uint4*)&Bh[br][bw * 8 + 4] = make_uint4(bh4, bh5, bh6, bh7);
            *(uint4*)&Bl[br][bw * 8]     = make_uint4(bl0, bl1, bl2, bl3);
            *(uint4*)&Bl[br][bw * 8 + 4] = make_uint4(bl4, bl5, bl6, bl7);
        }
        if (c + 1 < EMB / 32) {
            pa0 = *(const float4*)(ap + (c + 1) * 32);
            pa1 = *(const float4*)(ap + (c + 1) * 32 + 16);
            pb0 = *(const float4*)(bp + (c + 1) * 32);
            pb1 = *(const float4*)(bp + (c + 1) * 32 + 4);
            pb2 = *(const float4*)(bp + (c + 1) * 32 + 8);
            pb3 = *(const float4*)(bp + (c + 1) * 32 + 12);
        }
        __syncthreads();

        #pragma unroll
        for (int kk = 0; kk < 2; ++kk) {
            uint32_t fah[2][4], fal[2][4], fbh[2][4], fbl[2][4];
            #pragma unroll
            for (int mi = 0; mi < 2; ++mi) {
                ldsm4(fah[mi], aAh[mi] + kk * 32);
                ldsm4(fal[mi], aAl[mi] + kk * 32);
            }
            #pragma unroll
            for (int p = 0; p < 2; ++p) {
                ldsm4(fbh[p], aBh[p] + kk * 32);
                ldsm4(fbl[p], aBl[p] + kk * 32);
            }
            #pragma unroll
            for (int mi = 0; mi < 2; ++mi) {
                #pragma unroll
                for (int ni = 0; ni < 4; ++ni) {
                    const int p = ni >> 1, q = (ni & 1) * 2;
                    uint32_t b0h = fbh[p][q], b1h = fbh[p][q + 1];
                    uint32_t b0l = fbl[p][q], b1l = fbl[p][q + 1];
                    mma_bf16(d[mi][ni], fah[mi], b0h, b1h);
                    mma_bf16(d[mi][ni], fah[mi], b0l, b1l);
                    mma_bf16(d[mi][ni], fal[mi], b0h, b1h);
                }
            }
        }
    }

    #pragma unroll
    for (int mi = 0; mi < 2; ++mi) {
        int m = bm + wm + mi * 16 + g;
        #pragma unroll
        for (int ni = 0; ni < 4; ++ni) {
            int n = bn + wn + ni * 8 + 2 * t4;
            *(float2*)(C + (size_t)m * EMB + n)       = make_float2(d[mi][ni][0], d[mi][ni][1]);
            *(float2*)(C + (size_t)(m + 8) * EMB + n) = make_float2(d[mi][ni][2], d[mi][ni][3]);
        }
    }
}

// ===========================================================================
// Tensor-core flash attention v5:
//  - S = QK^T: bf16 2-split via m16n8k16 + ldmatrix (unchanged, validated).
//  - PV: P fragments built DIRECTLY from S accumulators (C-frag == A-frag
//    identity for m16n8 -> m16k16), P 2-split bf16; V staged as bf16 hi/lo
//    planes and loaded as B-fragments via ldmatrix.x4.trans.
//    No shuffles, no scalar LDS in PV.
//  - double-buffered smem (72KB), occupancy 2.
// ===========================================================================
#define KROWB  144
#define PLANE  (64 * KROWB)          // 9216
#define KBUFB  (2 * PLANE)           // 18432 (hi+lo)
#define VBUFB  (2 * PLANE)           // 18432 (hi+lo)
#define OFF_V  (2 * KBUFB)           // 36864
#define ATTN_SMEM (2 * KBUFB + 2 * VBUFB)   // 73728

__global__ __launch_bounds__(256, 2)
void attn_mma_kernel(const float* __restrict__ Q, const float* __restrict__ Kg,
                     const float* __restrict__ Vg, const uint32_t* __restrict__ Mp,
                     float* __restrict__ O)
{
    extern __shared__ char smem[];
    const uint32_t sbase = smem_u32(smem);

    const int tid  = threadIdx.x;
    const int lane = tid & 31;
    const int wid  = tid >> 5;
    const int g    = lane >> 2;
    const int t4   = lane & 3;
    const int h    = blockIdx.y;
    const int qb   = blockIdx.x;
    const int hb   = h * HD;
    const int row0 = qb * 128 + wid * 16;

    // ---- Q fragments: bf16 hi/lo, resident in regs ----
    uint32_t qfh[4][4], qfl[4][4];
    #pragma unroll
    for (int s = 0; s < 4; ++s) {
        const float* qr0 = Q + (size_t)(row0 + g)     * EMB + hb + 16 * s + 2 * t4;
        const float* qr1 = Q + (size_t)(row0 + g + 8) * EMB + hb + 16 * s + 2 * t4;
        float x0 = qr0[0] * 0.125f, x1 = qr0[1] * 0.125f;
        float y0 = qr1[0] * 0.125f, y1 = qr1[1] * 0.125f;
        float z0 = qr0[8] * 0.125f, z1 = qr0[9] * 0.125f;
        float w0 = qr1[8] * 0.125f, w1 = qr1[9] * 0.125f;
        qfh[s][0] = cvt2bf(x0, x1);
        qfl[s][0] = cvt2bf(x0 - bf_lowf(qfh[s][0]), x1 - bf_highf(qfh[s][0]));
        qfh[s][1] = cvt2bf(y0, y1);
        qfl[s][1] = cvt2bf(y0 - bf_lowf(qfh[s][1]), y1 - bf_highf(qfh[s][1]));
        qfh[s][2] = cvt2bf(z0, z1);
        qfl[s][2] = cvt2bf(z0 - bf_lowf(qfh[s][2]), z1 - bf_highf(qfh[s][2]));
        qfh[s][3] = cvt2bf(w0, w1);
        qfl[s][3] = cvt2bf(w0 - bf_lowf(qfh[s][3]), w1 - bf_highf(qfh[s][3]));
    }

    float o[8][4];
    #pragma unroll
    for (int ni = 0; ni < 8; ++ni)
        #pragma unroll
        for (int r = 0; r < 4; ++r) o[ni][r] = 0.f;
    float m0 = -1.0e30f, m1 = -1.0e30f;
    float l0 = 0.f, l1 = 0.f;

    // staging coordinates
    const int key = tid >> 2;          // key row this thread stages (0..63)
    const int qq  = tid & 3;           // 16-dim segment
    const float* kbase = Kg + (size_t)key * EMB + hb + qq * 16;
    const float* vbase = Vg + (size_t)key * EMB + hb + qq * 16;

    // ldmatrix read addresses
    const int brow  = (lane & 7) + ((lane >> 4) << 3);
    const int bkoff = ((lane >> 3) & 1) * 16;
    const uint32_t kaddr0 = sbase + brow * KROWB + bkoff;
    // V trans address: rows keyed by (lane&15), col block by (lane>>4)*8
    const uint32_t vaddr0 = sbase + OFF_V + (lane & 15) * KROWB + ((lane >> 4) << 3) * 2;

    const int rbase = wid * 16 + g;
    const uint32_t* mp0 = Mp + ((size_t)h * Lq + qb * 128 + rbase) * (Lq / 32);
    const uint32_t* mp1 = mp0 + 8 * (Lq / 32);

    // bf16 hi/lo split of a 16-float row segment to smem planes
    #define STAGE_HALF(SRC, DSTBYTE) do {                                        \
        float4 x0 = *(const float4*)(SRC);                                       \
        float4 x1 = *(const float4*)((SRC) + 4);                                 \
        float4 x2 = *(const float4*)((SRC) + 8);                                 \
        float4 x3 = *(const float4*)((SRC) + 12);                                \
        uint32_t h0 = cvt2bf(x0.x, x0.y), h1 = cvt2bf(x0.z, x0.w);               \
        uint32_t h2 = cvt2bf(x1.x, x1.y), h3 = cvt2bf(x1.z, x1.w);               \
        uint32_t h4 = cvt2bf(x2.x, x2.y), h5 = cvt2bf(x2.z, x2.w);               \
        uint32_t h6 = cvt2bf(x3.x, x3.y), h7 = cvt2bf(x3.z, x3.w);               \
        uint32_t l0_ = cvt2bf(x0.x - bf_lowf(h0), x0.y - bf_highf(h0));          \
        uint32_t l1_ = cvt2bf(x0.z - bf_lowf(h1), x0.w - bf_highf(h1));          \
        uint32_t l2_ = cvt2bf(x1.x - bf_lowf(h2), x1.y - bf_highf(h2));          \
        uint32_t l3_ = cvt2bf(x1.z - bf_lowf(h3), x1.w - bf_highf(h3));          \
        uint32_t l4_ = cvt2bf(x2.x - bf_lowf(h4), x2.y - bf_highf(h4));          \
        uint32_t l5_ = cvt2bf(x2.z - bf_lowf(h5), x2.w - bf_highf(h5));          \
        uint32_t l6_ = cvt2bf(x3.x - bf_lowf(h6), x3.y - bf_highf(h6));          \
        uint32_t l7_ = cvt2bf(x3.z - bf_lowf(h7), x3.w - bf_highf(h7));          \
        char* dst = smem + (DSTBYTE);                                            \
        *(uint4*)(dst)               = make_uint4(h0, h1, h2, h3);               \
        *(uint4*)(dst + 16)          = make_uint4(h4, h5, h6, h7);               \
        *(uint4*)(dst + PLANE)       = make_uint4(l0_, l1_, l2_, l3_);           \
        *(uint4*)(dst + PLANE + 16)  = make_uint4(l4_, l5_, l6_, l7_);           \
    } while (0)

    #define STAGE_TILE(T, BUF) do {                                              \
        STAGE_HALF(kbase + (size_t)(T) * 64 * EMB,                               \
                   (BUF) * KBUFB + key * KROWB + qq * 32);                       \
        STAGE_HALF(vbase + (size_t)(T) * 64 * EMB,                               \
                   OFF_V + (BUF) * VBUFB + key * KROWB + qq * 32);               \
    } while (0)

    STAGE_TILE(0, 0);
    __syncthreads();

    #pragma unroll 1
    for (int kt = 0; kt < NT; ++kt) {
        const int b = kt & 1;

        uint32_t cm0 = mp0[kt * 2],     cm1 = mp0[kt * 2 + 1];
        uint32_t cm2 = mp1[kt * 2],     cm3 = mp1[kt * 2 + 1];

        if (kt + 1 < NT) STAGE_TILE(kt + 1, b ^ 1);

        // ================= S = Q K^T (bf16 2-split via ldmatrix) ===========
        float s[8][4];
        #pragma unroll
        for (int ni = 0; ni < 8; ++ni)
            #pragma unroll
            for (int r = 0; r < 4; ++r) s[ni][r] = 0.f;

        const uint32_t ka = kaddr0 + b * KBUFB;
        #pragma unroll
        for (int sstep = 0; sstep < 4; ++sstep) {
            #pragma unroll
            for (int p = 0; p < 4; ++p) {
                uint32_t fh[4], fl[4];
                ldsm4(fh, ka + p * 16 * KROWB + sstep * 32);
                ldsm4(fl, ka + p * 16 * KROWB + sstep * 32 + PLANE);
                #pragma unroll
                for (int q = 0; q < 2; ++q) {
                    const int ni = 2 * p + q;
                    mma_bf16(s[ni], qfh[sstep], fh[2 * q], fh[2 * q + 1]);
                    mma_bf16(s[ni], qfh[sstep], fl[2 * q], fl[2 * q + 1]);
                    mma_bf16(s[ni], qfl[sstep], fh[2 * q], fh[2 * q + 1]);
                }
            }
        }

        // ================= masked online softmax ===========================
        float tm0 = -1.0e30f, tm1 = -1.0e30f;
        #pragma unroll
        for (int ni = 0; ni < 8; ++ni) {
            uint32_t wr0 = (ni < 4) ? cm0 : cm1;
            uint32_t wr1 = (ni < 4) ? cm2 : cm3;
            int b2 = 8 * (ni & 3) + 2 * t4;
            tm0 = fmaxf(tm0, ((wr0 >> b2) & 1u)       ? -1.0e30f : s[ni][0]);
            tm0 = fmaxf(tm0, ((wr0 >> (b2 + 1)) & 1u) ? -1.0e30f : s[ni][1]);
            tm1 = fmaxf(tm1, ((wr1 >> b2) & 1u)       ? -1.0e30f : s[ni][2]);
            tm1 = fmaxf(tm1, ((wr1 >> (b2 + 1)) & 1u) ? -1.0e30f : s[ni][3]);
        }
        tm0 = fmaxf(tm0, __shfl_xor_sync(0xffffffffu, tm0, 1));
        tm0 = fmaxf(tm0, __shfl_xor_sync(0xffffffffu, tm0, 2));
        tm1 = fmaxf(tm1, __shfl_xor_sync(0xffffffffu, tm1, 1));
        tm1 = fmaxf(tm1, __shfl_xor_sync(0xffffffffu, tm1, 2));

        float mn0 = fmaxf(m0, tm0), mn1 = fmaxf(m1, tm1);
        float c0 = __expf(m0 - mn0), c1 = __expf(m1 - mn1);
        m0 = mn0; m1 = mn1;

        float rs0 = 0.f, rs1 = 0.f;
        #pragma unroll
        for (int ni = 0; ni < 8; ++ni) {
            uint32_t wr0 = (ni < 4) ? cm0 : cm1;
            uint32_t wr1 = (ni < 4) ? cm2 : cm3;
            int b2 = 8 * (ni & 3) + 2 * t4;
            float p0 = ((wr0 >> b2) & 1u)       ? 0.f : __expf(s[ni][0] - mn0);
            float p1 = ((wr0 >> (b2 + 1)) & 1u) ? 0.f : __expf(s[ni][1] - mn0);
            float p2 = ((wr1 >> b2) & 1u)       ? 0.f : __expf(s[ni][2] - mn1);
            float p3 = ((wr1 >> (b2 + 1)) & 1u) ? 0.f : __expf(s[ni][3] - mn1);
            s[ni][0] = p0; s[ni][1] = p1; s[ni][2] = p2; s[ni][3] = p3;
            rs0 += p0 + p1; rs1 += p2 + p3;
        }
        rs0 += __shfl_xor_sync(0xffffffffu, rs0, 1);
        rs0 += __shfl_xor_sync(0xffffffffu, rs0, 2);
        rs1 += __shfl_xor_sync(0xffffffffu, rs1, 1);
        rs1 += __shfl_xor_sync(0xffffffffu, rs1, 2);
        l0 = l0 * c0 + rs0;
        l1 = l1 * c1 + rs1;

        #pragma unroll
        for (int ni = 0; ni < 8; ++ni) {
            o[ni][0] *= c0; o[ni][1] *= c0;
            o[ni][2] *= c1; o[ni][3] *= c1;
        }

        // ================= O += P V (bf16, register-direct P) ==============
        // C-frag of S IS the A-frag of PV: for k-step s,
        //   a0 = pack(s[2s][0],s[2s][1]), a1 = pack(s[2s][2],s[2s][3]),
        //   a2 = pack(s[2s+1][0],s[2s+1][1]), a3 = pack(s[2s+1][2],s[2s+1][3]).
        // V B-frags via ldmatrix.x4.trans on bf16 [key][dim] planes.
        {
            const uint32_t va = vaddr0 + b * VBUFB;
            #pragma unroll
            for (int st = 0; st < 4; ++st) {
                uint32_t ph[4], pl[4];
                #pragma unroll
                for (int half = 0; half < 2; ++half) {
                    const float v0 = s[2 * st + half][0], v1 = s[2 * st + half][1];
                    const float v2 = s[2 * st + half][2], v3 = s[2 * st + half][3];
                    ph[2 * half + 0] = cvt2bf(v0, v1);
                    pl[2 * half + 0] = cvt2bf(v0 - bf_lowf(ph[2 * half]), v1 - bf_highf(ph[2 * half]));
                    ph[2 * half + 1] = cvt2bf(v2, v3);
                    pl[2 * half + 1] = cvt2bf(v2 - bf_lowf(ph[2 * half + 1]), v3 - bf_highf(ph[2 * half + 1]));
                }
                // reorder to A-frag {a0,a1,a2,a3} = {s[2s](g), s[2s](g+8), s[2s+1](g), s[2s+1](g+8)}
                uint32_t ah[4] = {ph[0], ph[1], ph[2], ph[3]};
                uint32_t al[4] = {pl[0], pl[1], pl[2], pl[3]};
                #pragma unroll
                for (int np = 0; np < 4; ++np) {
                    uint32_t bh[4], bl[4];
                    ldsm4t(bh, va + st * (16 * KROWB) + np * 32);
                    ldsm4t(bl, va + st * (16 * KROWB) + np * 32 + PLANE);
                    mma_bf16(o[2 * np],     ah, bh[0], bh[1]);
                    mma_bf16(o[2 * np],     ah, bl[0], bl[1]);
                    mma_bf16(o[2 * np],     al, bh[0], bh[1]);
                    mma_bf16(o[2 * np + 1], ah, bh[2], bh[3]);
                    mma_bf16(o[2 * np + 1], ah, bl[2], bl[3]);
                    mma_bf16(o[2 * np + 1], al, bh[2], bh[3]);
                }
            }
        }

        __syncthreads();
    }

    // ================= epilogue =================
    float inv0 = (l0 > 0.f) ? (1.f / l0) : 0.f;
    float inv1 = (l1 > 0.f) ? (1.f / l1) : 0.f;
    #pragma unroll
    for (int ni = 0; ni < 8; ++ni) {
        int col = hb + 8 * ni + 2 * t4;
        *(float2*)(O + (size_t)(row0 + g)     * EMB + col) =
            make_float2(o[ni][0] * inv0, o[ni][1] * inv0);
        *(float2*)(O + (size_t)(row0 + g + 8) * EMB + col) =
            make_float2(o[ni][2] * inv1, o[ni][3] * inv1);
    }
}

// ---------------------------------------------------------------------------
extern "C" void kernel_launch(void* const* d_in, const int* in_sizes, int n_in,
                              void* d_out, int out_size)
{
    const float* q    = (const float*)d_in[0];
    const float* k    = (const float*)d_in[1];
    const float* v    = (const float*)d_in[2];
    const int*   mask = (const int*)d_in[3];
    const float* Wq   = (const float*)d_in[4];
    const float* Wk   = (const float*)d_in[5];
    const float* Wv   = (const float*)d_in[6];
    const float* Wo   = (const float*)d_in[7];
    float*       out  = (float*)d_out;

    float *gQ, *gK, *gV, *gA;
    uint32_t* gMp;
    cudaGetSymbolAddress((void**)&gQ, g_Q);
    cudaGetSymbolAddress((void**)&gK, g_K);
    cudaGetSymbolAddress((void**)&gV, g_V);
    cudaGetSymbolAddress((void**)&gA, g_A);
    cudaGetSymbolAddress((void**)&gMp, g_Mp);

    cudaFuncSetAttribute(attn_mma_kernel,
                         cudaFuncAttributeMaxDynamicSharedMemorySize, ATTN_SMEM);

    maskpack_kernel<<<2048, 256>>>(mask, gMp);

    dim3 ggrid(EMB / 128, Lq / 64);    // (8, 32) = 256 CTAs

    gemm_mma_kernel<<<ggrid, 256>>>(q, Wq, gQ);
    gemm_mma_kernel<<<ggrid, 256>>>(k, Wk, gK);
    gemm_mma_kernel<<<ggrid, 256>>>(v, Wv, gV);

    dim3 agrid(Lq / 128, NHEAD);       // (16, 16)
    attn_mma_kernel<<<agrid, 256, ATTN_SMEM>>>(gQ, gK, gV, gMp, gA);

    gemm_mma_kernel<<<ggrid, 256>>>(gA, Wo, out);
}

// round 13
// speedup vs baseline: 1.6926x; 1.1230x over previous
#include <cuda_runtime.h>
#include <cuda_bf16.h>
#include <cuda_fp16.h>
#include <stdint.h>

#define Lq     2048
#define EMB    1024
#define NHEAD  16
#define HD     64
#define NT     (Lq / 64)                       // key tiles
#define MP_WORDS (NHEAD * Lq * (Lq / 32))      // packed mask words

// Scratch (allocation-free rule: device globals)
__device__ float    g_Q[Lq * EMB];
__device__ float    g_K[Lq * EMB];
__device__ float    g_V[Lq * EMB];
__device__ float    g_A[Lq * EMB];
__device__ uint32_t g_Mp[MP_WORDS];            // bit-packed mask (8 MB)

__device__ __forceinline__ uint32_t smem_u32(const void* p) {
    uint32_t a;
    asm("{ .reg .u64 t; cvta.to.shared.u64 t, %1; cvt.u32.u64 %0, t; }" : "=r"(a) : "l"(p));
    return a;
}
// pack two floats -> bf16x2 (x0 low half, x1 high half)
__device__ __forceinline__ uint32_t cvt2bf(float x0, float x1) {
    uint32_t r;
    asm("cvt.rn.bf16x2.f32 %0, %1, %2;" : "=r"(r) : "f"(x1), "f"(x0));
    return r;
}
__device__ __forceinline__ float bf_lowf(uint32_t h)  { return __uint_as_float(h << 16); }
__device__ __forceinline__ float bf_highf(uint32_t h) { return __uint_as_float(h & 0xffff0000u); }

// pack two floats -> fp16x2
__device__ __forceinline__ uint32_t cvt2h(float x0, float x1) {
    __half2 h = __floats2half2_rn(x0, x1);
    return *reinterpret_cast<uint32_t*>(&h);
}
__device__ __forceinline__ float h_lowf(uint32_t h) {
    __half2 hh = *reinterpret_cast<__half2*>(&h);
    return __low2float(hh);
}
__device__ __forceinline__ float h_highf(uint32_t h) {
    __half2 hh = *reinterpret_cast<__half2*>(&h);
    return __high2float(hh);
}

// m16n8k16 bf16 HMMA (GEMM path)
__device__ __forceinline__ void mma_bf16(float d[4], const uint32_t a[4],
                                         const uint32_t b0, const uint32_t b1) {
    asm volatile(
        "mma.sync.aligned.m16n8k16.row.col.f32.bf16.bf16.f32 "
        "{%0,%1,%2,%3}, {%4,%5,%6,%7}, {%8,%9}, {%0,%1,%2,%3};\n"
        : "+f"(d[0]), "+f"(d[1]), "+f"(d[2]), "+f"(d[3])
        : "r"(a[0]), "r"(a[1]), "r"(a[2]), "r"(a[3]), "r"(b0), "r"(b1));
}
// m16n8k16 fp16 HMMA (attention path)
__device__ __forceinline__ void mma_f16(float d[4], const uint32_t a[4],
                                        const uint32_t b0, const uint32_t b1) {
    asm volatile(
        "mma.sync.aligned.m16n8k16.row.col.f32.f16.f16.f32 "
        "{%0,%1,%2,%3}, {%4,%5,%6,%7}, {%8,%9}, {%0,%1,%2,%3};\n"
        : "+f"(d[0]), "+f"(d[1]), "+f"(d[2]), "+f"(d[3])
        : "r"(a[0]), "r"(a[1]), "r"(a[2]), "r"(a[3]), "r"(b0), "r"(b1));
}

__device__ __forceinline__ void ldsm4(uint32_t r[4], uint32_t addr) {
    asm volatile("ldmatrix.sync.aligned.m8n8.x4.shared.b16 {%0,%1,%2,%3}, [%4];"
                 : "=r"(r[0]), "=r"(r[1]), "=r"(r[2]), "=r"(r[3]) : "r"(addr));
}
__device__ __forceinline__ void ldsm4t(uint32_t r[4], uint32_t addr) {
    asm volatile("ldmatrix.sync.aligned.m8n8.x4.trans.shared.b16 {%0,%1,%2,%3}, [%4];"
                 : "=r"(r[0]), "=r"(r[1]), "=r"(r[2]), "=r"(r[3]) : "r"(addr));
}

// ===========================================================================
// Mask bit-pack: int32[H*L*L] -> u32 bits (ballot).
// ===========================================================================
__global__ __launch_bounds__(256)
void maskpack_kernel(const int* __restrict__ mask, uint32_t* __restrict__ mp)
{
    const int lane = threadIdx.x & 31;
    const int wgid = (blockIdx.x * blockDim.x + threadIdx.x) >> 5;
    const int nw   = (gridDim.x * blockDim.x) >> 5;
    for (int w = wgid; w < MP_WORDS; w += nw) {
        int v = mask[(size_t)w * 32 + lane];
        uint32_t bits = __ballot_sync(0xffffffffu, v != 0);
        if (lane == 0) mp[w] = bits;
    }
}

// ===========================================================================
// bf16 3xsplit NT GEMM body (validated R9-R12). BK=32.
// CTA tile 64x128, 8 warps (2m x 4n), warp 32x32.
// ===========================================================================
__device__ __forceinline__ void gemm_body(const float* __restrict__ A,
                                          const float* __restrict__ B,
                                          float* __restrict__ C,
                                          int bm, int bn)
{
    __shared__ uint32_t Ah[64][20],  Al[64][20];    // 64 rows x 80B
    __shared__ uint32_t Bh[128][20], Bl[128][20];   // 128 rows x 80B

    const int tid  = threadIdx.x;
    const int lane = tid & 31;
    const int wid  = tid >> 5;
    const int g    = lane >> 2;
    const int t4   = lane & 3;
    const int wm   = (wid & 1) * 32;
    const int wn   = (wid >> 1) * 32;

    const int ar = tid >> 2, aw = tid & 3;
    const int br = tid >> 1, bw = tid & 1;
    const float* ap = A + (size_t)(bm + ar) * EMB + aw * 4;
    const float* bp = B + (size_t)(bn + br) * EMB + bw * 16;

    const uint32_t sAh = smem_u32(Ah), sAl = smem_u32(Al);
    const uint32_t sBh = smem_u32(Bh), sBl = smem_u32(Bl);
    const int arow = lane & 15, akoff = (lane >> 4) * 16;
    const int brow = (lane & 7) + ((lane >> 4) << 3);
    const int bkoff = ((lane >> 3) & 1) * 16;
    uint32_t aAh[2], aAl[2], aBh[2], aBl[2];
    #pragma unroll
    for (int mi = 0; mi < 2; ++mi) {
        aAh[mi] = sAh + (wm + 16 * mi + arow) * 80 + akoff;
        aAl[mi] = sAl + (wm + 16 * mi + arow) * 80 + akoff;
    }
    #pragma unroll
    for (int p = 0; p < 2; ++p) {
        aBh[p] = sBh + (wn + 16 * p + brow) * 80 + bkoff;
        aBl[p] = sBl + (wn + 16 * p + brow) * 80 + bkoff;
    }

    float d[2][4][4];
    #pragma unroll
    for (int i = 0; i < 2; ++i)
        #pragma unroll
        for (int j = 0; j < 4; ++j)
            #pragma unroll
            for (int r = 0; r < 4; ++r) d[i][j][r] = 0.f;

    float4 pa0 = *(const float4*)(ap);
    float4 pa1 = *(const float4*)(ap + 16);
    float4 pb0 = *(const float4*)(bp);
    float4 pb1 = *(const float4*)(bp + 4);
    float4 pb2 = *(const float4*)(bp + 8);
    float4 pb3 = *(const float4*)(bp + 12);

    #pragma unroll 1
    for (int c = 0; c < EMB / 32; ++c) {
        __syncthreads();
        {
            uint32_t h0 = cvt2bf(pa0.x, pa0.y), h1 = cvt2bf(pa0.z, pa0.w);
            uint32_t l0 = cvt2bf(pa0.x - bf_lowf(h0), pa0.y - bf_highf(h0));
            uint32_t l1 = cvt2bf(pa0.z - bf_lowf(h1), pa0.w - bf_highf(h1));
            *(uint2*)&Ah[ar][aw * 2] = make_uint2(h0, h1);
            *(uint2*)&Al[ar][aw * 2] = make_uint2(l0, l1);
            h0 = cvt2bf(pa1.x, pa1.y); h1 = cvt2bf(pa1.z, pa1.w);
            l0 = cvt2bf(pa1.x - bf_lowf(h0), pa1.y - bf_highf(h0));
            l1 = cvt2bf(pa1.z - bf_lowf(h1), pa1.w - bf_highf(h1));
            *(uint2*)&Ah[ar][aw * 2 + 8] = make_uint2(h0, h1);
            *(uint2*)&Al[ar][aw * 2 + 8] = make_uint2(l0, l1);

            uint32_t bh0 = cvt2bf(pb0.x, pb0.y), bh1 = cvt2bf(pb0.z, pb0.w);
            uint32_t bh2 = cvt2bf(pb1.x, pb1.y), bh3 = cvt2bf(pb1.z, pb1.w);
            uint32_t bh4 = cvt2bf(pb2.x, pb2.y), bh5 = cvt2bf(pb2.z, pb2.w);
            uint32_t bh6 = cvt2bf(pb3.x, pb3.y), bh7 = cvt2bf(pb3.z, pb3.w);
            uint32_t bl0 = cvt2bf(pb0.x - bf_lowf(bh0), pb0.y - bf_highf(bh0));
            uint32_t bl1 = cvt2bf(pb0.z - bf_lowf(bh1), pb0.w - bf_highf(bh1));
            uint32_t bl2 = cvt2bf(pb1.x - bf_lowf(bh2), pb1.y - bf_highf(bh2));
            uint32_t bl3 = cvt2bf(pb1.z - bf_lowf(bh3), pb1.w - bf_highf(bh3));
            uint32_t bl4 = cvt2bf(pb2.x - bf_lowf(bh4), pb2.y - bf_highf(bh4));
            uint32_t bl5 = cvt2bf(pb2.z - bf_lowf(bh5), pb2.w - bf_highf(bh5));
            uint32_t bl6 = cvt2bf(pb3.x - bf_lowf(bh6), pb3.y - bf_highf(bh6));
            uint32_t bl7 = cvt2bf(pb3.z - bf_lowf(bh7), pb3.w - bf_highf(bh7));
            *(uint4*)&Bh[br][bw * 8]     = make_uint4(bh0, bh1, bh2, bh3);
            *(uint4*)&Bh[br][bw * 8 + 4] = make_uint4(bh4, bh5, bh6, bh7);
            *(uint4*)&Bl[br][bw * 8]     = make_uint4(bl0, bl1, bl2, bl3);
            *(uint4*)&Bl[br][bw * 8 + 4] = make_uint4(bl4, bl5, bl6, bl7);
        }
        if (c + 1 < EMB / 32) {
            pa0 = *(const float4*)(ap + (c + 1) * 32);
            pa1 = *(const float4*)(ap + (c + 1) * 32 + 16);
            pb0 = *(const float4*)(bp + (c + 1) * 32);
            pb1 = *(const float4*)(bp + (c + 1) * 32 + 4);
            pb2 = *(const float4*)(bp + (c + 1) * 32 + 8);
            pb3 = *(const float4*)(bp + (c + 1) * 32 + 12);
        }
        __syncthreads();

        #pragma unroll
        for (int kk = 0; kk < 2; ++kk) {
            uint32_t fah[2][4], fal[2][4], fbh[2][4], fbl[2][4];
            #pragma unroll
            for (int mi = 0; mi < 2; ++mi) {
                ldsm4(fah[mi], aAh[mi] + kk * 32);
                ldsm4(fal[mi], aAl[mi] + kk * 32);
            }
            #pragma unroll
            for (int p = 0; p < 2; ++p) {
                ldsm4(fbh[p], aBh[p] + kk * 32);
                ldsm4(fbl[p], aBl[p] + kk * 32);
            }
            #pragma unroll
            for (int mi = 0; mi < 2; ++mi) {
                #pragma unroll
                for (int ni = 0; ni < 4; ++ni) {
                    const int p = ni >> 1, q = (ni & 1) * 2;
                    uint32_t b0h = fbh[p][q], b1h = fbh[p][q + 1];
                    uint32_t b0l = fbl[p][q], b1l = fbl[p][q + 1];
                    mma_bf16(d[mi][ni], fah[mi], b0h, b1h);
                    mma_bf16(d[mi][ni], fah[mi], b0l, b1l);
                    mma_bf16(d[mi][ni], fal[mi], b0h, b1h);
                }
            }
        }
    }

    #pragma unroll
    for (int mi = 0; mi < 2; ++mi) {
        int m = bm + wm + mi * 16 + g;
        #pragma unroll
        for (int ni = 0; ni < 4; ++ni) {
            int n = bn + wn + ni * 8 + 2 * t4;
            *(float2*)(C + (size_t)m * EMB + n)       = make_float2(d[mi][ni][0], d[mi][ni][1]);
            *(float2*)(C + (size_t)(m + 8) * EMB + n) = make_float2(d[mi][ni][2], d[mi][ni][3]);
        }
    }
}

// fused QKV projection: blockIdx.z selects (input, weight, output)
__global__ __launch_bounds__(256, 2)
void gemm_qkv_kernel(const float* __restrict__ q, const float* __restrict__ k,
                     const float* __restrict__ v, const float* __restrict__ Wq,
                     const float* __restrict__ Wk, const float* __restrict__ Wv,
                     float* __restrict__ Qo, float* __restrict__ Ko,
                     float* __restrict__ Vo)
{
    const float* A = (blockIdx.z == 0) ? q : (blockIdx.z == 1) ? k : v;
    const float* B = (blockIdx.z == 0) ? Wq : (blockIdx.z == 1) ? Wk : Wv;
    float*       C = (blockIdx.z == 0) ? Qo : (blockIdx.z == 1) ? Ko : Vo;
    gemm_body(A, B, C, blockIdx.y * 64, blockIdx.x * 128);
}

__global__ __launch_bounds__(256, 2)
void gemm_mma_kernel(const float* __restrict__ A, const float* __restrict__ B,
                     float* __restrict__ C)
{
    gemm_body(A, B, C, blockIdx.y * 64, blockIdx.x * 128);
}

// ===========================================================================
// Tensor-core flash attention v7: FP16 (8x more precise than bf16; R12
// structure retained, error scaled by measured R12 / 8 ~= 3e-4):
//  - S = QK^T: Q fp16 2-split (registers), K fp16 SINGLE plane.
//  - PV: P SINGLE fp16 (direct from S accums), V fp16 2-split.
//  - 128 MMA + 48 LDSM per warp-tile. Smem 54KB, occ 2.
// ===========================================================================
#define KROWB  144
#define PLANE  (64 * KROWB)          // 9216
#define KBUFB  PLANE                 // K: hi only
#define VBUFB  (2 * PLANE)           // V: hi+lo
#define OFF_V  (2 * KBUFB)           // 18432
#define ATTN_SMEM (2 * KBUFB + 2 * VBUFB)   // 55296

__global__ __launch_bounds__(256, 2)
void attn_mma_kernel(const float* __restrict__ Q, const float* __restrict__ Kg,
                     const float* __restrict__ Vg, const uint32_t* __restrict__ Mp,
                     float* __restrict__ O)
{
    extern __shared__ char smem[];
    const uint32_t sbase = smem_u32(smem);

    const int tid  = threadIdx.x;
    const int lane = tid & 31;
    const int wid  = tid >> 5;
    const int g    = lane >> 2;
    const int t4   = lane & 3;
    const int h    = blockIdx.y;
    const int qb   = blockIdx.x;
    const int hb   = h * HD;
    const int row0 = qb * 128 + wid * 16;

    // ---- Q fragments: fp16 hi/lo, resident in regs ----
    uint32_t qfh[4][4], qfl[4][4];
    #pragma unroll
    for (int s = 0; s < 4; ++s) {
        const float* qr0 = Q + (size_t)(row0 + g)     * EMB + hb + 16 * s + 2 * t4;
        const float* qr1 = Q + (size_t)(row0 + g + 8) * EMB + hb + 16 * s + 2 * t4;
        float x0 = qr0[0] * 0.125f, x1 = qr0[1] * 0.125f;
        float y0 = qr1[0] * 0.125f, y1 = qr1[1] * 0.125f;
        float z0 = qr0[8] * 0.125f, z1 = qr0[9] * 0.125f;
        float w0 = qr1[8] * 0.125f, w1 = qr1[9] * 0.125f;
        qfh[s][0] = cvt2h(x0, x1);
        qfl[s][0] = cvt2h(x0 - h_lowf(qfh[s][0]), x1 - h_highf(qfh[s][0]));
        qfh[s][1] = cvt2h(y0, y1);
        qfl[s][1] = cvt2h(y0 - h_lowf(qfh[s][1]), y1 - h_highf(qfh[s][1]));
        qfh[s][2] = cvt2h(z0, z1);
        qfl[s][2] = cvt2h(z0 - h_lowf(qfh[s][2]), z1 - h_highf(qfh[s][2]));
        qfh[s][3] = cvt2h(w0, w1);
        qfl[s][3] = cvt2h(w0 - h_lowf(qfh[s][3]), w1 - h_highf(qfh[s][3]));
    }

    float o[8][4];
    #pragma unroll
    for (int ni = 0; ni < 8; ++ni)
        #pragma unroll
        for (int r = 0; r < 4; ++r) o[ni][r] = 0.f;
    float m0 = -1.0e30f, m1 = -1.0e30f;
    float l0 = 0.f, l1 = 0.f;

    // staging coordinates
    const int key = tid >> 2;          // key row this thread stages (0..63)
    const int qq  = tid & 3;           // 16-dim segment
    const float* kbase = Kg + (size_t)key * EMB + hb + qq * 16;
    const float* vbase = Vg + (size_t)key * EMB + hb + qq * 16;

    // ldmatrix read addresses
    const int brow  = (lane & 7) + ((lane >> 4) << 3);
    const int bkoff = ((lane >> 3) & 1) * 16;
    const uint32_t kaddr0 = sbase + brow * KROWB + bkoff;
    const uint32_t vaddr0 = sbase + OFF_V + (lane & 15) * KROWB + ((lane >> 4) << 3) * 2;

    const int rbase = wid * 16 + g;
    const uint32_t* mp0 = Mp + ((size_t)h * Lq + qb * 128 + rbase) * (Lq / 32);
    const uint32_t* mp1 = mp0 + 8 * (Lq / 32);

    // K: fp16 hi only
    #define STAGE_K(SRC, DSTBYTE) do {                                           \
        float4 x0 = *(const float4*)(SRC);                                       \
        float4 x1 = *(const float4*)((SRC) + 4);                                 \
        float4 x2 = *(const float4*)((SRC) + 8);                                 \
        float4 x3 = *(const float4*)((SRC) + 12);                                \
        char* dst = smem + (DSTBYTE);                                            \
        *(uint4*)(dst)      = make_uint4(cvt2h(x0.x, x0.y), cvt2h(x0.z, x0.w),   \
                                         cvt2h(x1.x, x1.y), cvt2h(x1.z, x1.w));  \
        *(uint4*)(dst + 16) = make_uint4(cvt2h(x2.x, x2.y), cvt2h(x2.z, x2.w),   \
                                         cvt2h(x3.x, x3.y), cvt2h(x3.z, x3.w));  \
    } while (0)

    // V: fp16 hi + lo planes
    #define STAGE_V(SRC, DSTBYTE) do {                                           \
        float4 x0 = *(const float4*)(SRC);                                       \
        float4 x1 = *(const float4*)((SRC) + 4);                                 \
        float4 x2 = *(const float4*)((SRC) + 8);                                 \
        float4 x3 = *(const float4*)((SRC) + 12);                                \
        uint32_t h0 = cvt2h(x0.x, x0.y), h1 = cvt2h(x0.z, x0.w);                 \
        uint32_t h2 = cvt2h(x1.x, x1.y), h3 = cvt2h(x1.z, x1.w);                 \
        uint32_t h4 = cvt2h(x2.x, x2.y), h5 = cvt2h(x2.z, x2.w);                 \
        uint32_t h6 = cvt2h(x3.x, x3.y), h7 = cvt2h(x3.z, x3.w);                 \
        uint32_t l0_ = cvt2h(x0.x - h_lowf(h0), x0.y - h_highf(h0));             \
        uint32_t l1_ = cvt2h(x0.z - h_lowf(h1), x0.w - h_highf(h1));             \
        uint32_t l2_ = cvt2h(x1.x - h_lowf(h2), x1.y - h_highf(h2));             \
        uint32_t l3_ = cvt2h(x1.z - h_lowf(h3), x1.w - h_highf(h3));             \
        uint32_t l4_ = cvt2h(x2.x - h_lowf(h4), x2.y - h_highf(h4));             \
        uint32_t l5_ = cvt2h(x2.z - h_lowf(h5), x2.w - h_highf(h5));             \
        uint32_t l6_ = cvt2h(x3.x - h_lowf(h6), x3.y - h_highf(h6));             \
        uint32_t l7_ = cvt2h(x3.z - h_lowf(h7), x3.w - h_highf(h7));             \
        char* dst = smem + (DSTBYTE);                                            \
        *(uint4*)(dst)               = make_uint4(h0, h1, h2, h3);               \
        *(uint4*)(dst + 16)          = make_uint4(h4, h5, h6, h7);               \
        *(uint4*)(dst + PLANE)       = make_uint4(l0_, l1_, l2_, l3_);           \
        *(uint4*)(dst + PLANE + 16)  = make_uint4(l4_, l5_, l6_, l7_);           \
    } while (0)

    #define STAGE_TILE(T, BUF) do {                                              \
        STAGE_K(kbase + (size_t)(T) * 64 * EMB,                                  \
                (BUF) * KBUFB + key * KROWB + qq * 32);                          \
        STAGE_V(vbase + (size_t)(T) * 64 * EMB,                                  \
                OFF_V + (BUF) * VBUFB + key * KROWB + qq * 32);                  \
    } while (0)

    STAGE_TILE(0, 0);
    __syncthreads();

    #pragma unroll 1
    for (int kt = 0; kt < NT; ++kt) {
        const int b = kt & 1;

        uint32_t cm0 = mp0[kt * 2],     cm1 = mp0[kt * 2 + 1];
        uint32_t cm2 = mp1[kt * 2],     cm3 = mp1[kt * 2 + 1];

        if (kt + 1 < NT) STAGE_TILE(kt + 1, b ^ 1);

        // ================= S = Q K^T (Q fp16 2-split x K fp16 single) ======
        float s[8][4];
        #pragma unroll
        for (int ni = 0; ni < 8; ++ni)
            #pragma unroll
            for (int r = 0; r < 4; ++r) s[ni][r] = 0.f;

        const uint32_t ka = kaddr0 + b * KBUFB;
        #pragma unroll
        for (int sstep = 0; sstep < 4; ++sstep) {
            #pragma unroll
            for (int p = 0; p < 4; ++p) {
                uint32_t fh[4];
                ldsm4(fh, ka + p * 16 * KROWB + sstep * 32);
                #pragma unroll
                for (int q = 0; q < 2; ++q) {
                    const int ni = 2 * p + q;
                    mma_f16(s[ni], qfh[sstep], fh[2 * q], fh[2 * q + 1]);
                    mma_f16(s[ni], qfl[sstep], fh[2 * q], fh[2 * q + 1]);
                }
            }
        }

        // ================= masked online softmax ===========================
        float tm0 = -1.0e30f, tm1 = -1.0e30f;
        #pragma unroll
        for (int ni = 0; ni < 8; ++ni) {
            uint32_t wr0 = (ni < 4) ? cm0 : cm1;
            uint32_t wr1 = (ni < 4) ? cm2 : cm3;
            int b2 = 8 * (ni & 3) + 2 * t4;
            tm0 = fmaxf(tm0, ((wr0 >> b2) & 1u)       ? -1.0e30f : s[ni][0]);
            tm0 = fmaxf(tm0, ((wr0 >> (b2 + 1)) & 1u) ? -1.0e30f : s[ni][1]);
            tm1 = fmaxf(tm1, ((wr1 >> b2) & 1u)       ? -1.0e30f : s[ni][2]);
            tm1 = fmaxf(tm1, ((wr1 >> (b2 + 1)) & 1u) ? -1.0e30f : s[ni][3]);
        }
        tm0 = fmaxf(tm0, __shfl_xor_sync(0xffffffffu, tm0, 1));
        tm0 = fmaxf(tm0, __shfl_xor_sync(0xffffffffu, tm0, 2));
        tm1 = fmaxf(tm1, __shfl_xor_sync(0xffffffffu, tm1, 1));
        tm1 = fmaxf(tm1, __shfl_xor_sync(0xffffffffu, tm1, 2));

        float mn0 = fmaxf(m0, tm0), mn1 = fmaxf(m1, tm1);
        float c0 = __expf(m0 - mn0), c1 = __expf(m1 - mn1);
        m0 = mn0; m1 = mn1;

        float rs0 = 0.f, rs1 = 0.f;
        #pragma unroll
        for (int ni = 0; ni < 8; ++ni) {
            uint32_t wr0 = (ni < 4) ? cm0 : cm1;
            uint32_t wr1 = (ni < 4) ? cm2 : cm3;
            int b2 = 8 * (ni & 3) + 2 * t4;
            float p0 = ((wr0 >> b2) & 1u)       ? 0.f : __expf(s[ni][0] - mn0);
            float p1 = ((wr0 >> (b2 + 1)) & 1u) ? 0.f : __expf(s[ni][1] - mn0);
            float p2 = ((wr1 >> b2) & 1u)       ? 0.f : __expf(s[ni][2] - mn1);
            float p3 = ((wr1 >> (b2 + 1)) & 1u) ? 0.f : __expf(s[ni][3] - mn1);
            s[ni][0] = p0; s[ni][1] = p1; s[ni][2] = p2; s[ni][3] = p3;
            rs0 += p0 + p1; rs1 += p2 + p3;
        }
        rs0 += __shfl_xor_sync(0xffffffffu, rs0, 1);
        rs0 += __shfl_xor_sync(0xffffffffu, rs0, 2);
        rs1 += __shfl_xor_sync(0xffffffffu, rs1, 1);
        rs1 += __shfl_xor_sync(0xffffffffu, rs1, 2);
        l0 = l0 * c0 + rs0;
        l1 = l1 * c1 + rs1;

        #pragma unroll
        for (int ni = 0; ni < 8; ++ni) {
            o[ni][0] *= c0; o[ni][1] *= c0;
            o[ni][2] *= c1; o[ni][3] *= c1;
        }

        // ================= O += P V (P single fp16, V fp16 2-split) ========
        {
            const uint32_t va = vaddr0 + b * VBUFB;
            #pragma unroll
            for (int st = 0; st < 4; ++st) {
                uint32_t ah[4];
                ah[0] = cvt2h(s[2 * st][0],     s[2 * st][1]);
                ah[1] = cvt2h(s[2 * st][2],     s[2 * st][3]);
                ah[2] = cvt2h(s[2 * st + 1][0], s[2 * st + 1][1]);
                ah[3] = cvt2h(s[2 * st + 1][2], s[2 * st + 1][3]);
                #pragma unroll
                for (int np = 0; np < 4; ++np) {
                    uint32_t bh[4], bl[4];
                    ldsm4t(bh, va + st * (16 * KROWB) + np * 32);
                    ldsm4t(bl, va + st * (16 * KROWB) + np * 32 + PLANE);
                    mma_f16(o[2 * np],     ah, bh[0], bh[1]);
                    mma_f16(o[2 * np],     ah, bl[0], bl[1]);
                    mma_f16(o[2 * np + 1], ah, bh[2], bh[3]);
                    mma_f16(o[2 * np + 1], ah, bl[2], bl[3]);
                }
            }
        }

        __syncthreads();
    }

    // ================= epilogue =================
    float inv0 = (l0 > 0.f) ? (1.f / l0) : 0.f;
    float inv1 = (l1 > 0.f) ? (1.f / l1) : 0.f;
    #pragma unroll
    for (int ni = 0; ni < 8; ++ni) {
        int col = hb + 8 * ni + 2 * t4;
        *(float2*)(O + (size_t)(row0 + g)     * EMB + col) =
            make_float2(o[ni][0] * inv0, o[ni][1] * inv0);
        *(float2*)(O + (size_t)(row0 + g + 8) * EMB + col) =
            make_float2(o[ni][2] * inv1, o[ni][3] * inv1);
    }
}

// ---------------------------------------------------------------------------
extern "C" void kernel_launch(void* const* d_in, const int* in_sizes, int n_in,
                              void* d_out, int out_size)
{
    const float* q    = (const float*)d_in[0];
    const float* k    = (const float*)d_in[1];
    const float* v    = (const float*)d_in[2];
    const int*   mask = (const int*)d_in[3];
    const float* Wq   = (const float*)d_in[4];
    const float* Wk   = (const float*)d_in[5];
    const float* Wv   = (const float*)d_in[6];
    const float* Wo   = (const float*)d_in[7];
    float*       out  = (float*)d_out;

    float *gQ, *gK, *gV, *gA;
    uint32_t* gMp;
    cudaGetSymbolAddress((void**)&gQ, g_Q);
    cudaGetSymbolAddress((void**)&gK, g_K);
    cudaGetSymbolAddress((void**)&gV, g_V);
    cudaGetSymbolAddress((void**)&gA, g_A);
    cudaGetSymbolAddress((void**)&gMp, g_Mp);

    cudaFuncSetAttribute(attn_mma_kernel,
                         cudaFuncAttributeMaxDynamicSharedMemorySize, ATTN_SMEM);

    maskpack_kernel<<<2048, 256>>>(mask, gMp);

    dim3 qkvgrid(EMB / 128, Lq / 64, 3);   // (8, 32, 3) = 768 CTAs
    gemm_qkv_kernel<<<qkvgrid, 256>>>(q, k, v, Wq, Wk, Wv, gQ, gK, gV);

    dim3 agrid(Lq / 128, NHEAD);           // (16, 16)
    attn_mma_kernel<<<agrid, 256, ATTN_SMEM>>>(gQ, gK, gV, gMp, gA);

    dim3 ggrid(EMB / 128, Lq / 64);        // (8, 32)
    gemm_mma_kernel<<<ggrid, 256>>>(gA, Wo, out);
}